// round 14
// baseline (speedup 1.0000x reference)
#include <cuda_runtime.h>
#include <cuda_fp16.h>
#include <math.h>
#include <stdint.h>

#define B_ 1024
#define S_ 254
#define C_ 2
#define H_ 1024
#define K0P 256
#define NSTEPS 50
#define DT 0.02f

// ===================== helpers =============================================
__device__ __forceinline__ uint32_t smem_to_u32(const void* p) {
    uint32_t a;
    asm("{ .reg .u64 t; cvta.to.shared.u64 t, %1; cvt.u32.u64 %0, t; }" : "=r"(a) : "l"(p));
    return a;
}
#define CP_ASYNC16(dst, src) \
    asm volatile("cp.async.cg.shared.global [%0], [%1], 16;" :: "r"(dst), "l"(src) : "memory")
#define CP_COMMIT() asm volatile("cp.async.commit_group;" ::: "memory")
#define CP_WAIT1() asm volatile("cp.async.wait_group 1;" ::: "memory")

// PDL
#define GDC_WAIT()   asm volatile("griddepcontrol.wait;" ::: "memory")
#define GDC_LAUNCH() asm volatile("griddepcontrol.launch_dependents;" ::: "memory")

__device__ __forceinline__ void ldsm4(uint32_t* r, uint32_t addr) {
    asm volatile("ldmatrix.sync.aligned.m8n8.x4.shared.b16 {%0,%1,%2,%3}, [%4];"
        : "=r"(r[0]), "=r"(r[1]), "=r"(r[2]), "=r"(r[3]) : "r"(addr));
}
__device__ __forceinline__ void mma16816h(float* c, const uint32_t* a, const uint32_t* b) {
    asm volatile("mma.sync.aligned.m16n8k16.row.col.f32.f16.f16.f32 "
        "{%0,%1,%2,%3}, {%4,%5,%6,%7}, {%8,%9}, {%0,%1,%2,%3};"
        : "+f"(c[0]), "+f"(c[1]), "+f"(c[2]), "+f"(c[3])
        : "r"(a[0]), "r"(a[1]), "r"(a[2]), "r"(a[3]), "r"(b[0]), "r"(b[1]));
}

__device__ __forceinline__ float silu_f(float v) { return v / (1.0f + __expf(-v)); }

// ===================== scratch (device globals, no allocs) ==================
__device__ __half g_base0h[B_ * H_];
__device__ __half g_tvech[NSTEPS * H_];
__device__ __half g_w254h[H_];
__device__ __half g_w255h[H_];
__device__ float g_x[B_ * C_];
__device__ __half g_actA[B_ * H_];
__device__ __half g_actB[B_ * H_];
__device__ __half g_w16[3][H_ * H_];        // fp16 [N,K] transposed
__device__ __half g_state16[B_ * K0P];      // state fp16, K padded 254->256
__device__ __half g_w0t16[H_ * K0P];        // W0[0:254,:]^T fp16, padded
__device__ float g_part[8 * 16 * 128 * 2];  // [mblock][nblock][row][c]

// ===================== weight transpose to fp16 (all 3 layers, z) ===========
__global__ void wconv_kernel(const float* __restrict__ W1,
                             const float* __restrict__ W2,
                             const float* __restrict__ W3,
                             __half* __restrict__ w16) {
    __shared__ float t[32][33];
    const float* W = (blockIdx.z == 0) ? W1 : (blockIdx.z == 1) ? W2 : W3;
    __half* dst = w16 + (size_t)blockIdx.z * H_ * H_;
    const int k0 = blockIdx.y * 32, n0 = blockIdx.x * 32;
    const int tx = threadIdx.x, ty = threadIdx.y;
    for (int i = ty; i < 32; i += 8)
        t[i][tx] = W[(size_t)(k0 + i) * H_ + n0 + tx];
    __syncthreads();
    for (int i = ty; i < 32; i += 8)
        dst[(size_t)(n0 + i) * H_ + k0 + tx] = __float2half_rn(t[tx][i]);
}

// ===================== W0 head transpose (K padded to 256) ==================
// w0t16[n][k] = W0[k][n] for k<254 else 0.  grid (32, 8) tiles of 32x32.
__global__ void w0t_kernel(const float* __restrict__ W0, __half* __restrict__ w0t) {
    __shared__ float t[32][33];
    const int k0 = blockIdx.y * 32, n0 = blockIdx.x * 32;
    const int tx = threadIdx.x, ty = threadIdx.y;
    for (int i = ty; i < 32; i += 8) {
        int k = k0 + i;
        t[i][tx] = (k < S_) ? W0[(size_t)k * H_ + n0 + tx] : 0.0f;
    }
    __syncthreads();
    for (int i = ty; i < 32; i += 8)
        w0t[(size_t)(n0 + i) * K0P + k0 + tx] = __float2half_rn(t[tx][i]);
}

// ===================== state -> fp16 padded =================================
__global__ void state_conv_kernel(const float* __restrict__ state,
                                  __half* __restrict__ s16) {
    const int idx = blockIdx.x * 256 + threadIdx.x;   // < B_*K0P
    const int b = idx >> 8;
    const int k = idx & 255;
    s16[idx] = (k < S_) ? __float2half_rn(state[(size_t)b * S_ + k]) : __ushort_as_half(0);
}

// ===================== w254/w255 fp16 conversion ============================
__global__ void wrow_kernel(const float* __restrict__ w254,
                            const float* __restrict__ w255,
                            __half* __restrict__ h254, __half* __restrict__ h255) {
    const int j = blockIdx.x * 256 + threadIdx.x;
    h254[j] = __float2half_rn(w254[j]);
    h255[j] = __float2half_rn(w255[j]);
}

// ===================== time-embedding contribution (fp16 out) ===============
__global__ __launch_bounds__(128) void tvec_kernel(const float* __restrict__ W0,
                                                   __half* __restrict__ tvech) {
    __shared__ float temb[64];
    const int step = blockIdx.x;
    const int tid = threadIdx.x;
    const float t = (float)step * DT;
    if (tid < 64) {
        int k = tid & 31;
        float freq = expf(-9.210340371976184f * (float)k / 31.0f);
        float ang = t * freq;
        temb[tid] = (tid < 32) ? sinf(ang) : cosf(ang);
    }
    __syncthreads();
    const int j = blockIdx.y * 128 + tid;
    float acc = 0.0f;
    #pragma unroll
    for (int k = 0; k < 64; k++)
        acc += temb[k] * W0[(size_t)(256 + k) * H_ + j];
    tvech[step * H_ + j] = __float2half_rn(acc);
}

// ===================== fp16 HMMA GEMM common (BK=64, 3 stages) ==============
#define GBM 128
#define GBN 64
#define GBK 64
#define GSTAGES 3
#define OFF_A 0
#define OFF_B 16384
#define STAGE_BYTES 24576
#define GSMEM_TOTAL (GSTAGES * STAGE_BYTES)

__device__ __forceinline__ uint32_t soff(int r, int ch) {
    return (uint32_t)(r * 128 + (((ch ^ r) & 7) << 4));
}

// Parametrized: LDA_ = K-stride of A and W; NKT_ = K / 64.
// Weights (B) prefetched BEFORE griddepcontrol.wait; A after.
// launch_dependents fires after the LAST cp.async stage is issued (kt==NKT_-3).
#define GEMM_MAINLOOP(A_, W_, LDA_, NKT_)                                               \
    auto load_A = [&](int kt) {                                                         \
        const uint32_t sb = sbase + (uint32_t)(kt % GSTAGES) * STAGE_BYTES;             \
        const int kb = kt * GBK;                                                        \
        _Pragma("unroll")                                                               \
        for (int i = 0; i < 4; i++) {                                                   \
            int c = tid + i * 256;                                                      \
            int r = c >> 3, ch = c & 7;                                                 \
            CP_ASYNC16(sb + OFF_A + soff(r, ch), A_ + (size_t)(row0 + r) * LDA_ + kb + ch * 8); \
        }                                                                               \
    };                                                                                  \
    auto load_B = [&](int kt) {                                                         \
        const uint32_t sb = sbase + (uint32_t)(kt % GSTAGES) * STAGE_BYTES;             \
        const int kb = kt * GBK;                                                        \
        _Pragma("unroll")                                                               \
        for (int i = 0; i < 2; i++) {                                                   \
            int c = tid + i * 256;                                                      \
            int r = c >> 3, ch = c & 7;                                                 \
            CP_ASYNC16(sb + OFF_B + soff(r, ch), W_ + (size_t)(col0 + r) * LDA_ + kb + ch * 8); \
        }                                                                               \
    };                                                                                  \
    const int a_r = wm * 32 + (lane & 15);                                              \
    const int a_half = lane >> 4;                                                       \
    const int b_r = wn * 32 + (lane & 7) + ((lane >> 4) << 3);                          \
    const int b_half = (lane >> 3) & 1;                                                 \
    load_B(0); load_B(1);          /* weights: independent of predecessor */            \
    GDC_WAIT();                    /* block until predecessor grid flushed */           \
    load_A(0); CP_COMMIT();        /* group0 = B0,B1,A0 */                              \
    load_A(1); CP_COMMIT();        /* group1 = A1 */                                    \
    uint32_t af[2][2][4];                                                               \
    uint32_t bf[2][2][4];                                                               \
    const int NKT = (NKT_);                                                             \
    for (int kt = 0; kt < NKT; kt++) {                                                  \
        CP_WAIT1();                                                                     \
        __syncthreads();                                                                \
        const uint32_t sb = sbase + (uint32_t)(kt % GSTAGES) * STAGE_BYTES;             \
        _Pragma("unroll")                                                               \
        for (int mi = 0; mi < 2; mi++)                                                  \
            ldsm4(af[0][mi], sb + OFF_A + soff(a_r + mi * 16, a_half));                 \
        _Pragma("unroll")                                                               \
        for (int nt = 0; nt < 2; nt++)                                                  \
            ldsm4(bf[0][nt], sb + OFF_B + soff(b_r + nt * 16, b_half));                 \
        _Pragma("unroll")                                                               \
        for (int ks = 0; ks < 4; ks++) {                                                \
            const int cur = ks & 1, nxt = cur ^ 1;                                      \
            if (ks < 3) {                                                               \
                const int ch = (ks + 1) * 2;                                            \
                _Pragma("unroll")                                                       \
                for (int mi = 0; mi < 2; mi++)                                          \
                    ldsm4(af[nxt][mi], sb + OFF_A + soff(a_r + mi * 16, ch + a_half));  \
                _Pragma("unroll")                                                       \
                for (int nt = 0; nt < 2; nt++)                                          \
                    ldsm4(bf[nxt][nt], sb + OFF_B + soff(b_r + nt * 16, ch + b_half));  \
            }                                                                           \
            if (ks == 0) {                                                              \
                if (kt + 2 < NKT) { load_A(kt + 2); load_B(kt + 2); }                   \
                CP_COMMIT();                                                            \
                if (kt == NKT - 3) GDC_LAUNCH();  /* last stage issued */               \
            }                                                                           \
            _Pragma("unroll")                                                           \
            for (int mi = 0; mi < 2; mi++)                                              \
                _Pragma("unroll")                                                       \
                for (int ni = 0; ni < 4; ni++)                                          \
                    mma16816h(acc[mi][ni], af[cur][mi], &bf[cur][ni >> 1][(ni & 1) * 2]); \
        }                                                                               \
    }

// ---- variant 1: silu + fp16 store (layers 1, 2) ----
__global__ __launch_bounds__(256, 1) void gemm_hmma(
    const __half* __restrict__ A, const __half* __restrict__ W,
    const float* __restrict__ bias, __half* __restrict__ outC)
{
    extern __shared__ __align__(1024) char gs[];
    const uint32_t sbase = smem_to_u32(gs);
    const int tid = threadIdx.x;
    const int row0 = blockIdx.y * GBM;
    const int col0 = blockIdx.x * GBN;
    const int lane = tid & 31;
    const int wid = tid >> 5;
    const int wm = wid & 3;
    const int wn = wid >> 2;

    float acc[2][4][4];
    #pragma unroll
    for (int mi = 0; mi < 2; mi++)
        #pragma unroll
        for (int ni = 0; ni < 4; ni++)
            #pragma unroll
            for (int q = 0; q < 4; q++) acc[mi][ni][q] = 0.0f;

    GEMM_MAINLOOP(A, W, H_, 16)

    #pragma unroll
    for (int mi = 0; mi < 2; mi++) {
        const int r0g = row0 + wm * 32 + mi * 16 + (lane >> 2);
        #pragma unroll
        for (int ni = 0; ni < 4; ni++) {
            const int cg = col0 + wn * 32 + ni * 8 + (lane & 3) * 2;
            float2 bb = *reinterpret_cast<const float2*>(bias + cg);
            __half2 p0 = __floats2half2_rn(silu_f(acc[mi][ni][0] + bb.x),
                                           silu_f(acc[mi][ni][1] + bb.y));
            __half2 p1 = __floats2half2_rn(silu_f(acc[mi][ni][2] + bb.x),
                                           silu_f(acc[mi][ni][3] + bb.y));
            *reinterpret_cast<__half2*>(outC + (size_t)r0g * H_ + cg) = p0;
            *reinterpret_cast<__half2*>(outC + (size_t)(r0g + 8) * H_ + cg) = p1;
        }
    }
}

// ---- variant 2: layer 3 — silu then fold output head, write partials ----
__global__ __launch_bounds__(256, 1) void gemm_hmma_last(
    const __half* __restrict__ A, const __half* __restrict__ W,
    const float* __restrict__ bias, const float* __restrict__ W4,
    float* __restrict__ part)
{
    extern __shared__ __align__(1024) char gs[];
    __shared__ float spart[128 * 2];
    const uint32_t sbase = smem_to_u32(gs);
    const int tid = threadIdx.x;
    const int row0 = blockIdx.y * GBM;
    const int col0 = blockIdx.x * GBN;
    const int lane = tid & 31;
    const int wid = tid >> 5;
    const int wm = wid & 3;
    const int wn = wid >> 2;

    float acc[2][4][4];
    #pragma unroll
    for (int mi = 0; mi < 2; mi++)
        #pragma unroll
        for (int ni = 0; ni < 4; ni++)
            #pragma unroll
            for (int q = 0; q < 4; q++) acc[mi][ni][q] = 0.0f;

    GEMM_MAINLOOP(A, W, H_, 16)

    const float2* w4 = reinterpret_cast<const float2*>(W4);
    float sum[2][2][2];  // [mi][rhalf][c]
    #pragma unroll
    for (int mi = 0; mi < 2; mi++)
        #pragma unroll
        for (int rh = 0; rh < 2; rh++) { sum[mi][rh][0] = 0.0f; sum[mi][rh][1] = 0.0f; }

    #pragma unroll
    for (int mi = 0; mi < 2; mi++) {
        #pragma unroll
        for (int ni = 0; ni < 4; ni++) {
            const int cg = col0 + wn * 32 + ni * 8 + (lane & 3) * 2;
            float2 bb = *reinterpret_cast<const float2*>(bias + cg);
            float2 w0 = w4[cg], w1 = w4[cg + 1];
            float h00 = silu_f(acc[mi][ni][0] + bb.x);
            float h01 = silu_f(acc[mi][ni][1] + bb.y);
            float h10 = silu_f(acc[mi][ni][2] + bb.x);
            float h11 = silu_f(acc[mi][ni][3] + bb.y);
            sum[mi][0][0] += h00 * w0.x + h01 * w1.x;
            sum[mi][0][1] += h00 * w0.y + h01 * w1.y;
            sum[mi][1][0] += h10 * w0.x + h11 * w1.x;
            sum[mi][1][1] += h10 * w0.y + h11 * w1.y;
        }
    }
    #pragma unroll
    for (int mi = 0; mi < 2; mi++)
        #pragma unroll
        for (int rh = 0; rh < 2; rh++)
            #pragma unroll
            for (int c = 0; c < 2; c++) {
                float v = sum[mi][rh][c];
                v += __shfl_xor_sync(0xffffffffu, v, 1);
                v += __shfl_xor_sync(0xffffffffu, v, 2);
                sum[mi][rh][c] = v;
            }
    if (wn == 0 && (lane & 3) == 0) {
        #pragma unroll
        for (int mi = 0; mi < 2; mi++)
            #pragma unroll
            for (int rh = 0; rh < 2; rh++) {
                int r = wm * 32 + mi * 16 + rh * 8 + (lane >> 2);
                spart[r * 2 + 0] = sum[mi][rh][0];
                spart[r * 2 + 1] = sum[mi][rh][1];
            }
    }
    __syncthreads();
    if (wn == 1 && (lane & 3) == 0) {
        #pragma unroll
        for (int mi = 0; mi < 2; mi++)
            #pragma unroll
            for (int rh = 0; rh < 2; rh++) {
                int r = wm * 32 + mi * 16 + rh * 8 + (lane >> 2);
                spart[r * 2 + 0] += sum[mi][rh][0];
                spart[r * 2 + 1] += sum[mi][rh][1];
            }
    }
    __syncthreads();
    float* dst = part + ((size_t)(blockIdx.y * 16 + blockIdx.x) * 256);
    if (tid < 256) dst[tid] = spart[tid];
}

// ---- variant 3: base0 GEMM (K=256, bias only, fp16 out) --------------------
__global__ __launch_bounds__(256, 1) void gemm_base0(
    const __half* __restrict__ A, const __half* __restrict__ W,
    const float* __restrict__ bias, __half* __restrict__ outC)
{
    extern __shared__ __align__(1024) char gs[];
    const uint32_t sbase = smem_to_u32(gs);
    const int tid = threadIdx.x;
    const int row0 = blockIdx.y * GBM;
    const int col0 = blockIdx.x * GBN;
    const int lane = tid & 31;
    const int wid = tid >> 5;
    const int wm = wid & 3;
    const int wn = wid >> 2;

    float acc[2][4][4];
    #pragma unroll
    for (int mi = 0; mi < 2; mi++)
        #pragma unroll
        for (int ni = 0; ni < 4; ni++)
            #pragma unroll
            for (int q = 0; q < 4; q++) acc[mi][ni][q] = 0.0f;

    GEMM_MAINLOOP(A, W, K0P, 4)

    #pragma unroll
    for (int mi = 0; mi < 2; mi++) {
        const int r0g = row0 + wm * 32 + mi * 16 + (lane >> 2);
        #pragma unroll
        for (int ni = 0; ni < 4; ni++) {
            const int cg = col0 + wn * 32 + ni * 8 + (lane & 3) * 2;
            float2 bb = *reinterpret_cast<const float2*>(bias + cg);
            __half2 p0 = __floats2half2_rn(acc[mi][ni][0] + bb.x, acc[mi][ni][1] + bb.y);
            __half2 p1 = __floats2half2_rn(acc[mi][ni][2] + bb.x, acc[mi][ni][3] + bb.y);
            *reinterpret_cast<__half2*>(outC + (size_t)r0g * H_ + cg) = p0;
            *reinterpret_cast<__half2*>(outC + (size_t)(r0g + 8) * H_ + cg) = p1;
        }
    }
}

// ===================== quarter-row layer0 body (all-fp16 inputs) ============
__device__ __forceinline__ void layer0_quarter(
    const __half* __restrict__ base0h, const __half* __restrict__ tvech,
    const __half* __restrict__ h254, const __half* __restrict__ h255,
    int row, int g, float xb0, float xb1, __half* __restrict__ hOut)
{
    const uint4* bsrc = reinterpret_cast<const uint4*>(base0h + (size_t)row * H_);
    const uint4* tsrc = reinterpret_cast<const uint4*>(tvech);
    const uint4* asrc = reinterpret_cast<const uint4*>(h254);
    const uint4* csrc = reinterpret_cast<const uint4*>(h255);
    uint4 bh = bsrc[g], th = tsrc[g], ah = asrc[g], ch = csrc[g];
    uint4 o;
    const uint32_t* bw = &bh.x;
    const uint32_t* tw = &th.x;
    const uint32_t* aw = &ah.x;
    const uint32_t* cw = &ch.x;
    uint32_t* ow = &o.x;
    #pragma unroll
    for (int w = 0; w < 4; w++) {
        float2 b = __half22float2(*reinterpret_cast<const __half2*>(&bw[w]));
        float2 t = __half22float2(*reinterpret_cast<const __half2*>(&tw[w]));
        float2 a = __half22float2(*reinterpret_cast<const __half2*>(&aw[w]));
        float2 c = __half22float2(*reinterpret_cast<const __half2*>(&cw[w]));
        float v0 = silu_f(b.x + t.x + xb0 * a.x + xb1 * c.x);
        float v1 = silu_f(b.y + t.y + xb0 * a.y + xb1 * c.y);
        *reinterpret_cast<__half2*>(&ow[w]) = __floats2half2_rn(v0, v1);
    }
    reinterpret_cast<uint4*>(hOut + (size_t)row * H_)[g] = o;
}

// ===================== layer-0 activation (step 0 only) =====================
__global__ __launch_bounds__(256) void layer0_act(
    const __half* __restrict__ base0h, const __half* __restrict__ tvec_step,
    const __half* __restrict__ h254, const __half* __restrict__ h255,
    const float* __restrict__ x, __half* __restrict__ h)
{
    const int tid = threadIdx.x;
    const int lane = tid & 31;
    const int wid = tid >> 5;
    const int row = blockIdx.x * 2 + (wid >> 2);
    const float xv0 = x[2 * row];
    const float xv1 = x[2 * row + 1];
    const int g = (wid & 3) * 32 + lane;
    layer0_quarter(base0h, tvec_step, h254, h255, row, g, xv0, xv1, h);
}

// ===================== fused: partial-sum + Euler + next-step layer0 ========
__global__ __launch_bounds__(256) void step_fuse(
    const float* __restrict__ part,
    const float* __restrict__ b4,
    float* __restrict__ x,
    const __half* __restrict__ base0h, const __half* __restrict__ tvec_next,
    const __half* __restrict__ h254, const __half* __restrict__ h255,
    __half* __restrict__ hOut)
{
    GDC_WAIT();
    GDC_LAUNCH();
    const int tid = threadIdx.x;
    const int lane = tid & 31;
    const int wid = tid >> 5;
    const int rbase = blockIdx.x * 2;

    __shared__ float sx[2][2];

    if (wid < 2) {
        const int row = rbase + wid;
        const int by = row >> 7, rl = row & 127;
        float v0 = 0.0f, v1 = 0.0f;
        if (lane < 16) {
            float2 p = *reinterpret_cast<const float2*>(
                part + ((size_t)(by * 16 + lane) * 128 + rl) * 2);
            v0 = p.x; v1 = p.y;
        }
        #pragma unroll
        for (int o = 8; o > 0; o >>= 1) {
            v0 += __shfl_down_sync(0xffffffffu, v0, o);
            v1 += __shfl_down_sync(0xffffffffu, v1, o);
        }
        if (lane == 0) {
            v0 = x[2 * row]     + DT * (v0 + b4[0]);
            v1 = x[2 * row + 1] + DT * (v1 + b4[1]);
            x[2 * row] = v0; x[2 * row + 1] = v1;
            sx[wid][0] = v0; sx[wid][1] = v1;
        }
    }
    __syncthreads();

    const int rl = wid >> 2;
    const int row = rbase + rl;
    const float xv0 = sx[rl][0];
    const float xv1 = sx[rl][1];
    const int g = (wid & 3) * 32 + lane;
    layer0_quarter(base0h, tvec_next, h254, h255, row, g, xv0, xv1, hOut);
}

// ===================== final: partial-sum + Euler -> out ====================
__global__ __launch_bounds__(256) void out_euler(
    const float* __restrict__ part,
    const float* __restrict__ b4,
    const float* __restrict__ x, float* __restrict__ out)
{
    GDC_WAIT();
    const int tid = threadIdx.x;
    const int lane = tid & 31;
    const int wid = tid >> 5;
    const int row = blockIdx.x * 8 + wid;
    const int by = row >> 7, rl = row & 127;
    float v0 = 0.0f, v1 = 0.0f;
    if (lane < 16) {
        float2 p = *reinterpret_cast<const float2*>(
            part + ((size_t)(by * 16 + lane) * 128 + rl) * 2);
        v0 = p.x; v1 = p.y;
    }
    #pragma unroll
    for (int o = 8; o > 0; o >>= 1) {
        v0 += __shfl_down_sync(0xffffffffu, v0, o);
        v1 += __shfl_down_sync(0xffffffffu, v1, o);
    }
    if (lane == 0) {
        out[2 * row]     = x[2 * row]     + DT * (v0 + b4[0]);
        out[2 * row + 1] = x[2 * row + 1] + DT * (v1 + b4[1]);
    }
}

// ===================== host side ============================================
template <typename KernelT, typename... Args>
static void launch_pdl(KernelT k, dim3 g, dim3 b, size_t smem, Args... args) {
    cudaLaunchConfig_t cfg = {};
    cfg.gridDim = g;
    cfg.blockDim = b;
    cfg.dynamicSmemBytes = smem;
    cfg.stream = 0;
    cudaLaunchAttribute at[1];
    at[0].id = cudaLaunchAttributeProgrammaticStreamSerialization;
    at[0].val.programmaticStreamSerializationAllowed = 1;
    cfg.attrs = at;
    cfg.numAttrs = 1;
    cudaLaunchKernelEx(&cfg, k, args...);
}

extern "C" void kernel_launch(void* const* d_in, const int* in_sizes, int n_in,
                              void* d_out, int out_size)
{
    const float* state = (const float*)d_in[0];
    const float* x0    = (const float*)d_in[1];
    const float* W0    = (const float*)d_in[2];
    const float* b0    = (const float*)d_in[3];
    const float* W1    = (const float*)d_in[4];
    const float* b1    = (const float*)d_in[5];
    const float* W2    = (const float*)d_in[6];
    const float* b2    = (const float*)d_in[7];
    const float* W3    = (const float*)d_in[8];
    const float* b3    = (const float*)d_in[9];
    const float* W4    = (const float*)d_in[10];
    const float* b4    = (const float*)d_in[11];
    float* out = (float*)d_out;

    float *xp, *partp;
    __half *base0h, *tvech, *h254, *h255, *actA, *actB, *w16, *s16, *w0t;
    cudaGetSymbolAddress((void**)&base0h, g_base0h);
    cudaGetSymbolAddress((void**)&tvech,  g_tvech);
    cudaGetSymbolAddress((void**)&h254,   g_w254h);
    cudaGetSymbolAddress((void**)&h255,   g_w255h);
    cudaGetSymbolAddress((void**)&xp,     g_x);
    cudaGetSymbolAddress((void**)&actA,   g_actA);
    cudaGetSymbolAddress((void**)&actB,   g_actB);
    cudaGetSymbolAddress((void**)&w16,    g_w16);
    cudaGetSymbolAddress((void**)&s16,    g_state16);
    cudaGetSymbolAddress((void**)&w0t,    g_w0t16);
    cudaGetSymbolAddress((void**)&partp,  g_part);

    static bool attr_set = false;
    if (!attr_set) {
        cudaFuncSetAttribute(gemm_hmma, cudaFuncAttributeMaxDynamicSharedMemorySize,
                             GSMEM_TOTAL);
        cudaFuncSetAttribute(gemm_hmma_last, cudaFuncAttributeMaxDynamicSharedMemorySize,
                             GSMEM_TOTAL);
        cudaFuncSetAttribute(gemm_base0, cudaFuncAttributeMaxDynamicSharedMemorySize,
                             GSMEM_TOTAL);
        attr_set = true;
    }

    // one-time prep (normal launches)
    cudaMemcpyAsync(xp, x0, B_ * C_ * sizeof(float), cudaMemcpyDeviceToDevice);
    wconv_kernel<<<dim3(32, 32, 3), dim3(32, 8)>>>(W1, W2, W3, w16);
    w0t_kernel<<<dim3(32, 8), dim3(32, 8)>>>(W0, w0t);
    state_conv_kernel<<<(B_ * K0P) / 256, 256>>>(state, s16);
    tvec_kernel<<<dim3(NSTEPS, 8), 128>>>(W0, tvech);
    wrow_kernel<<<4, 256>>>(W0 + (size_t)254 * H_, W0 + (size_t)255 * H_, h254, h255);

    dim3 ggrid(H_ / GBN, B_ / GBM);  // (16, 8) = 128 CTAs
    gemm_base0<<<ggrid, 256, GSMEM_TOTAL>>>(s16, w0t, b0, base0h);

    __half* wl0 = w16 + 0 * (size_t)H_ * H_;
    __half* wl1 = w16 + 1 * (size_t)H_ * H_;
    __half* wl2 = w16 + 2 * (size_t)H_ * H_;

    layer0_act<<<B_ / 2, 256>>>(base0h, tvech, h254, h255, xp, actA);
    for (int i = 0; i < NSTEPS; i++) {
        launch_pdl(gemm_hmma, ggrid, dim3(256), (size_t)GSMEM_TOTAL,
                   (const __half*)actA, (const __half*)wl0, b1, actB);
        launch_pdl(gemm_hmma, ggrid, dim3(256), (size_t)GSMEM_TOTAL,
                   (const __half*)actB, (const __half*)wl1, b2, actA);
        launch_pdl(gemm_hmma_last, ggrid, dim3(256), (size_t)GSMEM_TOTAL,
                   (const __half*)actA, (const __half*)wl2, b3, W4, partp);
        if (i + 1 < NSTEPS) {
            launch_pdl(step_fuse, dim3(B_ / 2), dim3(256), (size_t)0,
                       (const float*)partp, b4, xp, (const __half*)base0h,
                       (const __half*)(tvech + (size_t)(i + 1) * H_), h254, h255, actA);
        } else {
            launch_pdl(out_euler, dim3(B_ / 8), dim3(256), (size_t)0,
                       (const float*)partp, b4, (const float*)xp, out);
        }
    }
}

// round 15
// speedup vs baseline: 1.0187x; 1.0187x over previous
#include <cuda_runtime.h>
#include <cuda_fp16.h>
#include <math.h>
#include <stdint.h>

#define B_ 1024
#define S_ 254
#define C_ 2
#define H_ 1024
#define K0P 256
#define NSTEPS 50
#define DT 0.02f

// ===================== helpers =============================================
__device__ __forceinline__ uint32_t smem_to_u32(const void* p) {
    uint32_t a;
    asm("{ .reg .u64 t; cvta.to.shared.u64 t, %1; cvt.u32.u64 %0, t; }" : "=r"(a) : "l"(p));
    return a;
}
#define CP_ASYNC16(dst, src) \
    asm volatile("cp.async.cg.shared.global [%0], [%1], 16;" :: "r"(dst), "l"(src) : "memory")
#define CP_COMMIT() asm volatile("cp.async.commit_group;" ::: "memory")
#define CP_WAIT1() asm volatile("cp.async.wait_group 1;" ::: "memory")

// PDL
#define GDC_WAIT()   asm volatile("griddepcontrol.wait;" ::: "memory")
#define GDC_LAUNCH() asm volatile("griddepcontrol.launch_dependents;" ::: "memory")

__device__ __forceinline__ void ldsm4(uint32_t* r, uint32_t addr) {
    asm volatile("ldmatrix.sync.aligned.m8n8.x4.shared.b16 {%0,%1,%2,%3}, [%4];"
        : "=r"(r[0]), "=r"(r[1]), "=r"(r[2]), "=r"(r[3]) : "r"(addr));
}
__device__ __forceinline__ void mma16816h(float* c, const uint32_t* a, const uint32_t* b) {
    asm volatile("mma.sync.aligned.m16n8k16.row.col.f32.f16.f16.f32 "
        "{%0,%1,%2,%3}, {%4,%5,%6,%7}, {%8,%9}, {%0,%1,%2,%3};"
        : "+f"(c[0]), "+f"(c[1]), "+f"(c[2]), "+f"(c[3])
        : "r"(a[0]), "r"(a[1]), "r"(a[2]), "r"(a[3]), "r"(b[0]), "r"(b[1]));
}

__device__ __forceinline__ float silu_f(float v) { return v / (1.0f + __expf(-v)); }

// ===================== scratch (device globals, no allocs) ==================
__device__ __half g_base0h[B_ * H_];
__device__ __half g_tvech[NSTEPS * H_];
__device__ __half g_w254h[H_];
__device__ __half g_w255h[H_];
__device__ float g_x[B_ * C_];
__device__ __half g_actA[B_ * H_];
__device__ __half g_actB[B_ * H_];
__device__ __half g_w16[3][H_ * H_];        // fp16 [N,K] transposed
__device__ __half g_state16[B_ * K0P];      // state fp16, K padded 254->256
__device__ __half g_w0t16[H_ * K0P];        // W0[0:254,:]^T fp16, padded
__device__ float g_part[8 * 16 * 128 * 2];  // [mblock][nblock][row][c]

// ===================== weight transpose to fp16 (all 3 layers, z) ===========
__global__ void wconv_kernel(const float* __restrict__ W1,
                             const float* __restrict__ W2,
                             const float* __restrict__ W3,
                             __half* __restrict__ w16) {
    __shared__ float t[32][33];
    const float* W = (blockIdx.z == 0) ? W1 : (blockIdx.z == 1) ? W2 : W3;
    __half* dst = w16 + (size_t)blockIdx.z * H_ * H_;
    const int k0 = blockIdx.y * 32, n0 = blockIdx.x * 32;
    const int tx = threadIdx.x, ty = threadIdx.y;
    for (int i = ty; i < 32; i += 8)
        t[i][tx] = W[(size_t)(k0 + i) * H_ + n0 + tx];
    __syncthreads();
    for (int i = ty; i < 32; i += 8)
        dst[(size_t)(n0 + i) * H_ + k0 + tx] = __float2half_rn(t[tx][i]);
}

// ===================== W0 head transpose (K padded to 256) ==================
__global__ void w0t_kernel(const float* __restrict__ W0, __half* __restrict__ w0t) {
    __shared__ float t[32][33];
    const int k0 = blockIdx.y * 32, n0 = blockIdx.x * 32;
    const int tx = threadIdx.x, ty = threadIdx.y;
    for (int i = ty; i < 32; i += 8) {
        int k = k0 + i;
        t[i][tx] = (k < S_) ? W0[(size_t)k * H_ + n0 + tx] : 0.0f;
    }
    __syncthreads();
    for (int i = ty; i < 32; i += 8)
        w0t[(size_t)(n0 + i) * K0P + k0 + tx] = __float2half_rn(t[tx][i]);
}

// ===================== state -> fp16 padded =================================
__global__ void state_conv_kernel(const float* __restrict__ state,
                                  __half* __restrict__ s16) {
    const int idx = blockIdx.x * 256 + threadIdx.x;   // < B_*K0P
    const int b = idx >> 8;
    const int k = idx & 255;
    s16[idx] = (k < S_) ? __float2half_rn(state[(size_t)b * S_ + k]) : __ushort_as_half(0);
}

// ===================== w254/w255 fp16 conversion ============================
__global__ void wrow_kernel(const float* __restrict__ w254,
                            const float* __restrict__ w255,
                            __half* __restrict__ h254, __half* __restrict__ h255) {
    const int j = blockIdx.x * 256 + threadIdx.x;
    h254[j] = __float2half_rn(w254[j]);
    h255[j] = __float2half_rn(w255[j]);
}

// ===================== time-embedding contribution (fp16 out) ===============
__global__ __launch_bounds__(128) void tvec_kernel(const float* __restrict__ W0,
                                                   __half* __restrict__ tvech) {
    __shared__ float temb[64];
    const int step = blockIdx.x;
    const int tid = threadIdx.x;
    const float t = (float)step * DT;
    if (tid < 64) {
        int k = tid & 31;
        float freq = expf(-9.210340371976184f * (float)k / 31.0f);
        float ang = t * freq;
        temb[tid] = (tid < 32) ? sinf(ang) : cosf(ang);
    }
    __syncthreads();
    const int j = blockIdx.y * 128 + tid;
    float acc = 0.0f;
    #pragma unroll
    for (int k = 0; k < 64; k++)
        acc += temb[k] * W0[(size_t)(256 + k) * H_ + j];
    tvech[step * H_ + j] = __float2half_rn(acc);
}

// ===================== fp16 HMMA GEMM common (BK=64, 3 stages) ==============
#define GBM 128
#define GBN 64
#define GBK 64
#define GSTAGES 3
#define OFF_A 0
#define OFF_B 16384
#define STAGE_BYTES 24576
#define GSMEM_TOTAL (GSTAGES * STAGE_BYTES)

__device__ __forceinline__ uint32_t soff(int r, int ch) {
    return (uint32_t)(r * 128 + (((ch ^ r) & 7) << 4));
}

// Parametrized: LDA_ = K-stride of A and W; NKT_ = K / 64.
// Weights (B) prefetched BEFORE griddepcontrol.wait; A after.
// launch_dependents fires AFTER the mainloop (round-13 validated placement).
#define GEMM_MAINLOOP(A_, W_, LDA_, NKT_)                                               \
    auto load_A = [&](int kt) {                                                         \
        const uint32_t sb = sbase + (uint32_t)(kt % GSTAGES) * STAGE_BYTES;             \
        const int kb = kt * GBK;                                                        \
        _Pragma("unroll")                                                               \
        for (int i = 0; i < 4; i++) {                                                   \
            int c = tid + i * 256;                                                      \
            int r = c >> 3, ch = c & 7;                                                 \
            CP_ASYNC16(sb + OFF_A + soff(r, ch), A_ + (size_t)(row0 + r) * LDA_ + kb + ch * 8); \
        }                                                                               \
    };                                                                                  \
    auto load_B = [&](int kt) {                                                         \
        const uint32_t sb = sbase + (uint32_t)(kt % GSTAGES) * STAGE_BYTES;             \
        const int kb = kt * GBK;                                                        \
        _Pragma("unroll")                                                               \
        for (int i = 0; i < 2; i++) {                                                   \
            int c = tid + i * 256;                                                      \
            int r = c >> 3, ch = c & 7;                                                 \
            CP_ASYNC16(sb + OFF_B + soff(r, ch), W_ + (size_t)(col0 + r) * LDA_ + kb + ch * 8); \
        }                                                                               \
    };                                                                                  \
    const int a_r = wm * 32 + (lane & 15);                                              \
    const int a_half = lane >> 4;                                                       \
    const int b_r = wn * 32 + (lane & 7) + ((lane >> 4) << 3);                          \
    const int b_half = (lane >> 3) & 1;                                                 \
    load_B(0); load_B(1);          /* weights: independent of predecessor */            \
    GDC_WAIT();                    /* block until predecessor grid flushed */           \
    load_A(0); CP_COMMIT();        /* group0 = B0,B1,A0 */                              \
    load_A(1); CP_COMMIT();        /* group1 = A1 */                                    \
    uint32_t af[2][2][4];                                                               \
    uint32_t bf[2][2][4];                                                               \
    const int NKT = (NKT_);                                                             \
    for (int kt = 0; kt < NKT; kt++) {                                                  \
        CP_WAIT1();                                                                     \
        __syncthreads();                                                                \
        const uint32_t sb = sbase + (uint32_t)(kt % GSTAGES) * STAGE_BYTES;             \
        _Pragma("unroll")                                                               \
        for (int mi = 0; mi < 2; mi++)                                                  \
            ldsm4(af[0][mi], sb + OFF_A + soff(a_r + mi * 16, a_half));                 \
        _Pragma("unroll")                                                               \
        for (int nt = 0; nt < 2; nt++)                                                  \
            ldsm4(bf[0][nt], sb + OFF_B + soff(b_r + nt * 16, b_half));                 \
        _Pragma("unroll")                                                               \
        for (int ks = 0; ks < 4; ks++) {                                                \
            const int cur = ks & 1, nxt = cur ^ 1;                                      \
            if (ks < 3) {                                                               \
                const int ch = (ks + 1) * 2;                                            \
                _Pragma("unroll")                                                       \
                for (int mi = 0; mi < 2; mi++)                                          \
                    ldsm4(af[nxt][mi], sb + OFF_A + soff(a_r + mi * 16, ch + a_half));  \
                _Pragma("unroll")                                                       \
                for (int nt = 0; nt < 2; nt++)                                          \
                    ldsm4(bf[nxt][nt], sb + OFF_B + soff(b_r + nt * 16, ch + b_half));  \
            }                                                                           \
            if (ks == 0) {                                                              \
                if (kt + 2 < NKT) { load_A(kt + 2); load_B(kt + 2); }                   \
                CP_COMMIT();                                                            \
            }                                                                           \
            _Pragma("unroll")                                                           \
            for (int mi = 0; mi < 2; mi++)                                              \
                _Pragma("unroll")                                                       \
                for (int ni = 0; ni < 4; ni++)                                          \
                    mma16816h(acc[mi][ni], af[cur][mi], &bf[cur][ni >> 1][(ni & 1) * 2]); \
        }                                                                               \
    }                                                                                   \
    GDC_LAUNCH();   /* co-residency window = epilogue only */

// ---- variant 1: silu + fp16 store (layers 1, 2) ----
__global__ __launch_bounds__(256, 1) void gemm_hmma(
    const __half* __restrict__ A, const __half* __restrict__ W,
    const float* __restrict__ bias, __half* __restrict__ outC)
{
    extern __shared__ __align__(1024) char gs[];
    const uint32_t sbase = smem_to_u32(gs);
    const int tid = threadIdx.x;
    const int row0 = blockIdx.y * GBM;
    const int col0 = blockIdx.x * GBN;
    const int lane = tid & 31;
    const int wid = tid >> 5;
    const int wm = wid & 3;
    const int wn = wid >> 2;

    float acc[2][4][4];
    #pragma unroll
    for (int mi = 0; mi < 2; mi++)
        #pragma unroll
        for (int ni = 0; ni < 4; ni++)
            #pragma unroll
            for (int q = 0; q < 4; q++) acc[mi][ni][q] = 0.0f;

    GEMM_MAINLOOP(A, W, H_, 16)

    #pragma unroll
    for (int mi = 0; mi < 2; mi++) {
        const int r0g = row0 + wm * 32 + mi * 16 + (lane >> 2);
        #pragma unroll
        for (int ni = 0; ni < 4; ni++) {
            const int cg = col0 + wn * 32 + ni * 8 + (lane & 3) * 2;
            float2 bb = *reinterpret_cast<const float2*>(bias + cg);
            __half2 p0 = __floats2half2_rn(silu_f(acc[mi][ni][0] + bb.x),
                                           silu_f(acc[mi][ni][1] + bb.y));
            __half2 p1 = __floats2half2_rn(silu_f(acc[mi][ni][2] + bb.x),
                                           silu_f(acc[mi][ni][3] + bb.y));
            *reinterpret_cast<__half2*>(outC + (size_t)r0g * H_ + cg) = p0;
            *reinterpret_cast<__half2*>(outC + (size_t)(r0g + 8) * H_ + cg) = p1;
        }
    }
}

// ---- variant 2: layer 3 — silu then fold output head, write partials ----
__global__ __launch_bounds__(256, 1) void gemm_hmma_last(
    const __half* __restrict__ A, const __half* __restrict__ W,
    const float* __restrict__ bias, const float* __restrict__ W4,
    float* __restrict__ part)
{
    extern __shared__ __align__(1024) char gs[];
    __shared__ float spart[128 * 2];
    const uint32_t sbase = smem_to_u32(gs);
    const int tid = threadIdx.x;
    const int row0 = blockIdx.y * GBM;
    const int col0 = blockIdx.x * GBN;
    const int lane = tid & 31;
    const int wid = tid >> 5;
    const int wm = wid & 3;
    const int wn = wid >> 2;

    float acc[2][4][4];
    #pragma unroll
    for (int mi = 0; mi < 2; mi++)
        #pragma unroll
        for (int ni = 0; ni < 4; ni++)
            #pragma unroll
            for (int q = 0; q < 4; q++) acc[mi][ni][q] = 0.0f;

    GEMM_MAINLOOP(A, W, H_, 16)

    const float2* w4 = reinterpret_cast<const float2*>(W4);
    float sum[2][2][2];  // [mi][rhalf][c]
    #pragma unroll
    for (int mi = 0; mi < 2; mi++)
        #pragma unroll
        for (int rh = 0; rh < 2; rh++) { sum[mi][rh][0] = 0.0f; sum[mi][rh][1] = 0.0f; }

    #pragma unroll
    for (int mi = 0; mi < 2; mi++) {
        #pragma unroll
        for (int ni = 0; ni < 4; ni++) {
            const int cg = col0 + wn * 32 + ni * 8 + (lane & 3) * 2;
            float2 bb = *reinterpret_cast<const float2*>(bias + cg);
            float2 w0 = w4[cg], w1 = w4[cg + 1];
            float h00 = silu_f(acc[mi][ni][0] + bb.x);
            float h01 = silu_f(acc[mi][ni][1] + bb.y);
            float h10 = silu_f(acc[mi][ni][2] + bb.x);
            float h11 = silu_f(acc[mi][ni][3] + bb.y);
            sum[mi][0][0] += h00 * w0.x + h01 * w1.x;
            sum[mi][0][1] += h00 * w0.y + h01 * w1.y;
            sum[mi][1][0] += h10 * w0.x + h11 * w1.x;
            sum[mi][1][1] += h10 * w0.y + h11 * w1.y;
        }
    }
    #pragma unroll
    for (int mi = 0; mi < 2; mi++)
        #pragma unroll
        for (int rh = 0; rh < 2; rh++)
            #pragma unroll
            for (int c = 0; c < 2; c++) {
                float v = sum[mi][rh][c];
                v += __shfl_xor_sync(0xffffffffu, v, 1);
                v += __shfl_xor_sync(0xffffffffu, v, 2);
                sum[mi][rh][c] = v;
            }
    if (wn == 0 && (lane & 3) == 0) {
        #pragma unroll
        for (int mi = 0; mi < 2; mi++)
            #pragma unroll
            for (int rh = 0; rh < 2; rh++) {
                int r = wm * 32 + mi * 16 + rh * 8 + (lane >> 2);
                spart[r * 2 + 0] = sum[mi][rh][0];
                spart[r * 2 + 1] = sum[mi][rh][1];
            }
    }
    __syncthreads();
    if (wn == 1 && (lane & 3) == 0) {
        #pragma unroll
        for (int mi = 0; mi < 2; mi++)
            #pragma unroll
            for (int rh = 0; rh < 2; rh++) {
                int r = wm * 32 + mi * 16 + rh * 8 + (lane >> 2);
                spart[r * 2 + 0] += sum[mi][rh][0];
                spart[r * 2 + 1] += sum[mi][rh][1];
            }
    }
    __syncthreads();
    float* dst = part + ((size_t)(blockIdx.y * 16 + blockIdx.x) * 256);
    if (tid < 256) dst[tid] = spart[tid];
}

// ---- variant 3: base0 GEMM (K=256, bias only, fp16 out) --------------------
__global__ __launch_bounds__(256, 1) void gemm_base0(
    const __half* __restrict__ A, const __half* __restrict__ W,
    const float* __restrict__ bias, __half* __restrict__ outC)
{
    extern __shared__ __align__(1024) char gs[];
    const uint32_t sbase = smem_to_u32(gs);
    const int tid = threadIdx.x;
    const int row0 = blockIdx.y * GBM;
    const int col0 = blockIdx.x * GBN;
    const int lane = tid & 31;
    const int wid = tid >> 5;
    const int wm = wid & 3;
    const int wn = wid >> 2;

    float acc[2][4][4];
    #pragma unroll
    for (int mi = 0; mi < 2; mi++)
        #pragma unroll
        for (int ni = 0; ni < 4; ni++)
            #pragma unroll
            for (int q = 0; q < 4; q++) acc[mi][ni][q] = 0.0f;

    GEMM_MAINLOOP(A, W, K0P, 4)

    #pragma unroll
    for (int mi = 0; mi < 2; mi++) {
        const int r0g = row0 + wm * 32 + mi * 16 + (lane >> 2);
        #pragma unroll
        for (int ni = 0; ni < 4; ni++) {
            const int cg = col0 + wn * 32 + ni * 8 + (lane & 3) * 2;
            float2 bb = *reinterpret_cast<const float2*>(bias + cg);
            __half2 p0 = __floats2half2_rn(acc[mi][ni][0] + bb.x, acc[mi][ni][1] + bb.y);
            __half2 p1 = __floats2half2_rn(acc[mi][ni][2] + bb.x, acc[mi][ni][3] + bb.y);
            *reinterpret_cast<__half2*>(outC + (size_t)r0g * H_ + cg) = p0;
            *reinterpret_cast<__half2*>(outC + (size_t)(r0g + 8) * H_ + cg) = p1;
        }
    }
}

// ===================== quarter-row layer0 body (all-fp16 inputs) ============
__device__ __forceinline__ void layer0_quarter(
    const __half* __restrict__ base0h, const __half* __restrict__ tvech,
    const __half* __restrict__ h254, const __half* __restrict__ h255,
    int row, int g, float xb0, float xb1, __half* __restrict__ hOut)
{
    const uint4* bsrc = reinterpret_cast<const uint4*>(base0h + (size_t)row * H_);
    const uint4* tsrc = reinterpret_cast<const uint4*>(tvech);
    const uint4* asrc = reinterpret_cast<const uint4*>(h254);
    const uint4* csrc = reinterpret_cast<const uint4*>(h255);
    uint4 bh = bsrc[g], th = tsrc[g], ah = asrc[g], ch = csrc[g];
    uint4 o;
    const uint32_t* bw = &bh.x;
    const uint32_t* tw = &th.x;
    const uint32_t* aw = &ah.x;
    const uint32_t* cw = &ch.x;
    uint32_t* ow = &o.x;
    #pragma unroll
    for (int w = 0; w < 4; w++) {
        float2 b = __half22float2(*reinterpret_cast<const __half2*>(&bw[w]));
        float2 t = __half22float2(*reinterpret_cast<const __half2*>(&tw[w]));
        float2 a = __half22float2(*reinterpret_cast<const __half2*>(&aw[w]));
        float2 c = __half22float2(*reinterpret_cast<const __half2*>(&cw[w]));
        float v0 = silu_f(b.x + t.x + xb0 * a.x + xb1 * c.x);
        float v1 = silu_f(b.y + t.y + xb0 * a.y + xb1 * c.y);
        *reinterpret_cast<__half2*>(&ow[w]) = __floats2half2_rn(v0, v1);
    }
    reinterpret_cast<uint4*>(hOut + (size_t)row * H_)[g] = o;
}

// ===================== layer-0 activation (step 0 only) =====================
__global__ __launch_bounds__(256) void layer0_act(
    const __half* __restrict__ base0h, const __half* __restrict__ tvec_step,
    const __half* __restrict__ h254, const __half* __restrict__ h255,
    const float* __restrict__ x, __half* __restrict__ h)
{
    const int tid = threadIdx.x;
    const int lane = tid & 31;
    const int wid = tid >> 5;
    const int row = blockIdx.x * 2 + (wid >> 2);
    const float xv0 = x[2 * row];
    const float xv1 = x[2 * row + 1];
    const int g = (wid & 3) * 32 + lane;
    layer0_quarter(base0h, tvec_step, h254, h255, row, g, xv0, xv1, h);
}

// ===================== fused: partial-sum + Euler + next-step layer0 ========
__global__ __launch_bounds__(256) void step_fuse(
    const float* __restrict__ part,
    const float* __restrict__ b4,
    float* __restrict__ x,
    const __half* __restrict__ base0h, const __half* __restrict__ tvec_next,
    const __half* __restrict__ h254, const __half* __restrict__ h255,
    __half* __restrict__ hOut)
{
    GDC_WAIT();
    GDC_LAUNCH();
    const int tid = threadIdx.x;
    const int lane = tid & 31;
    const int wid = tid >> 5;
    const int rbase = blockIdx.x * 2;

    __shared__ float sx[2][2];

    if (wid < 2) {
        const int row = rbase + wid;
        const int by = row >> 7, rl = row & 127;
        float v0 = 0.0f, v1 = 0.0f;
        if (lane < 16) {
            float2 p = *reinterpret_cast<const float2*>(
                part + ((size_t)(by * 16 + lane) * 128 + rl) * 2);
            v0 = p.x; v1 = p.y;
        }
        #pragma unroll
        for (int o = 8; o > 0; o >>= 1) {
            v0 += __shfl_down_sync(0xffffffffu, v0, o);
            v1 += __shfl_down_sync(0xffffffffu, v1, o);
        }
        if (lane == 0) {
            v0 = x[2 * row]     + DT * (v0 + b4[0]);
            v1 = x[2 * row + 1] + DT * (v1 + b4[1]);
            x[2 * row] = v0; x[2 * row + 1] = v1;
            sx[wid][0] = v0; sx[wid][1] = v1;
        }
    }
    __syncthreads();

    const int rl = wid >> 2;
    const int row = rbase + rl;
    const float xv0 = sx[rl][0];
    const float xv1 = sx[rl][1];
    const int g = (wid & 3) * 32 + lane;
    layer0_quarter(base0h, tvec_next, h254, h255, row, g, xv0, xv1, hOut);
}

// ===================== final: partial-sum + Euler -> out ====================
__global__ __launch_bounds__(256) void out_euler(
    const float* __restrict__ part,
    const float* __restrict__ b4,
    const float* __restrict__ x, float* __restrict__ out)
{
    GDC_WAIT();
    const int tid = threadIdx.x;
    const int lane = tid & 31;
    const int wid = tid >> 5;
    const int row = blockIdx.x * 8 + wid;
    const int by = row >> 7, rl = row & 127;
    float v0 = 0.0f, v1 = 0.0f;
    if (lane < 16) {
        float2 p = *reinterpret_cast<const float2*>(
            part + ((size_t)(by * 16 + lane) * 128 + rl) * 2);
        v0 = p.x; v1 = p.y;
    }
    #pragma unroll
    for (int o = 8; o > 0; o >>= 1) {
        v0 += __shfl_down_sync(0xffffffffu, v0, o);
        v1 += __shfl_down_sync(0xffffffffu, v1, o);
    }
    if (lane == 0) {
        out[2 * row]     = x[2 * row]     + DT * (v0 + b4[0]);
        out[2 * row + 1] = x[2 * row + 1] + DT * (v1 + b4[1]);
    }
}

// ===================== host side ============================================
template <typename KernelT, typename... Args>
static void launch_pdl(KernelT k, dim3 g, dim3 b, size_t smem, Args... args) {
    cudaLaunchConfig_t cfg = {};
    cfg.gridDim = g;
    cfg.blockDim = b;
    cfg.dynamicSmemBytes = smem;
    cfg.stream = 0;
    cudaLaunchAttribute at[1];
    at[0].id = cudaLaunchAttributeProgrammaticStreamSerialization;
    at[0].val.programmaticStreamSerializationAllowed = 1;
    cfg.attrs = at;
    cfg.numAttrs = 1;
    cudaLaunchKernelEx(&cfg, k, args...);
}

extern "C" void kernel_launch(void* const* d_in, const int* in_sizes, int n_in,
                              void* d_out, int out_size)
{
    const float* state = (const float*)d_in[0];
    const float* x0    = (const float*)d_in[1];
    const float* W0    = (const float*)d_in[2];
    const float* b0    = (const float*)d_in[3];
    const float* W1    = (const float*)d_in[4];
    const float* b1    = (const float*)d_in[5];
    const float* W2    = (const float*)d_in[6];
    const float* b2    = (const float*)d_in[7];
    const float* W3    = (const float*)d_in[8];
    const float* b3    = (const float*)d_in[9];
    const float* W4    = (const float*)d_in[10];
    const float* b4    = (const float*)d_in[11];
    float* out = (float*)d_out;

    float *xp, *partp;
    __half *base0h, *tvech, *h254, *h255, *actA, *actB, *w16, *s16, *w0t;
    cudaGetSymbolAddress((void**)&base0h, g_base0h);
    cudaGetSymbolAddress((void**)&tvech,  g_tvech);
    cudaGetSymbolAddress((void**)&h254,   g_w254h);
    cudaGetSymbolAddress((void**)&h255,   g_w255h);
    cudaGetSymbolAddress((void**)&xp,     g_x);
    cudaGetSymbolAddress((void**)&actA,   g_actA);
    cudaGetSymbolAddress((void**)&actB,   g_actB);
    cudaGetSymbolAddress((void**)&w16,    g_w16);
    cudaGetSymbolAddress((void**)&s16,    g_state16);
    cudaGetSymbolAddress((void**)&w0t,    g_w0t16);
    cudaGetSymbolAddress((void**)&partp,  g_part);

    static bool attr_set = false;
    if (!attr_set) {
        cudaFuncSetAttribute(gemm_hmma, cudaFuncAttributeMaxDynamicSharedMemorySize,
                             GSMEM_TOTAL);
        cudaFuncSetAttribute(gemm_hmma_last, cudaFuncAttributeMaxDynamicSharedMemorySize,
                             GSMEM_TOTAL);
        cudaFuncSetAttribute(gemm_base0, cudaFuncAttributeMaxDynamicSharedMemorySize,
                             GSMEM_TOTAL);
        attr_set = true;
    }

    // one-time prep (normal launches)
    cudaMemcpyAsync(xp, x0, B_ * C_ * sizeof(float), cudaMemcpyDeviceToDevice);
    wconv_kernel<<<dim3(32, 32, 3), dim3(32, 8)>>>(W1, W2, W3, w16);
    w0t_kernel<<<dim3(32, 8), dim3(32, 8)>>>(W0, w0t);
    state_conv_kernel<<<(B_ * K0P) / 256, 256>>>(state, s16);
    tvec_kernel<<<dim3(NSTEPS, 8), 128>>>(W0, tvech);
    wrow_kernel<<<4, 256>>>(W0 + (size_t)254 * H_, W0 + (size_t)255 * H_, h254, h255);

    dim3 ggrid(H_ / GBN, B_ / GBM);  // (16, 8) = 128 CTAs
    gemm_base0<<<ggrid, 256, GSMEM_TOTAL>>>(s16, w0t, b0, base0h);

    __half* wl0 = w16 + 0 * (size_t)H_ * H_;
    __half* wl1 = w16 + 1 * (size_t)H_ * H_;
    __half* wl2 = w16 + 2 * (size_t)H_ * H_;

    layer0_act<<<B_ / 2, 256>>>(base0h, tvech, h254, h255, xp, actA);
    for (int i = 0; i < NSTEPS; i++) {
        launch_pdl(gemm_hmma, ggrid, dim3(256), (size_t)GSMEM_TOTAL,
                   (const __half*)actA, (const __half*)wl0, b1, actB);
        launch_pdl(gemm_hmma, ggrid, dim3(256), (size_t)GSMEM_TOTAL,
                   (const __half*)actB, (const __half*)wl1, b2, actA);
        launch_pdl(gemm_hmma_last, ggrid, dim3(256), (size_t)GSMEM_TOTAL,
                   (const __half*)actA, (const __half*)wl2, b3, W4, partp);
        if (i + 1 < NSTEPS) {
            launch_pdl(step_fuse, dim3(B_ / 2), dim3(256), (size_t)0,
                       (const float*)partp, b4, xp, (const __half*)base0h,
                       (const __half*)(tvech + (size_t)(i + 1) * H_), h254, h255, actA);
        } else {
            launch_pdl(out_euler, dim3(B_ / 8), dim3(256), (size_t)0,
                       (const float*)partp, b4, (const float*)xp, out);
        }
    }
}

// round 16
// speedup vs baseline: 1.0209x; 1.0021x over previous
#include <cuda_runtime.h>
#include <cuda_fp16.h>
#include <math.h>
#include <stdint.h>

#define B_ 1024
#define S_ 254
#define C_ 2
#define H_ 1024
#define K0P 256
#define NSTEPS 50
#define DT 0.02f

// ===================== helpers =============================================
__device__ __forceinline__ uint32_t smem_to_u32(const void* p) {
    uint32_t a;
    asm("{ .reg .u64 t; cvta.to.shared.u64 t, %1; cvt.u32.u64 %0, t; }" : "=r"(a) : "l"(p));
    return a;
}
#define CP_ASYNC16(dst, src) \
    asm volatile("cp.async.cg.shared.global [%0], [%1], 16;" :: "r"(dst), "l"(src) : "memory")
#define CP_COMMIT() asm volatile("cp.async.commit_group;" ::: "memory")
#define CP_WAIT1() asm volatile("cp.async.wait_group 1;" ::: "memory")

// PDL
#define GDC_WAIT()   asm volatile("griddepcontrol.wait;" ::: "memory")
#define GDC_LAUNCH() asm volatile("griddepcontrol.launch_dependents;" ::: "memory")

__device__ __forceinline__ void ldsm4(uint32_t* r, uint32_t addr) {
    asm volatile("ldmatrix.sync.aligned.m8n8.x4.shared.b16 {%0,%1,%2,%3}, [%4];"
        : "=r"(r[0]), "=r"(r[1]), "=r"(r[2]), "=r"(r[3]) : "r"(addr));
}
__device__ __forceinline__ void mma16816h(float* c, const uint32_t* a, const uint32_t* b) {
    asm volatile("mma.sync.aligned.m16n8k16.row.col.f32.f16.f16.f32 "
        "{%0,%1,%2,%3}, {%4,%5,%6,%7}, {%8,%9}, {%0,%1,%2,%3};"
        : "+f"(c[0]), "+f"(c[1]), "+f"(c[2]), "+f"(c[3])
        : "r"(a[0]), "r"(a[1]), "r"(a[2]), "r"(a[3]), "r"(b[0]), "r"(b[1]));
}

__device__ __forceinline__ float silu_f(float v) { return v / (1.0f + __expf(-v)); }

// ===================== scratch (device globals, no allocs) ==================
__device__ __half g_base0h[B_ * H_];
__device__ __half g_tvech[NSTEPS * H_];
__device__ __half g_w254h[H_];
__device__ __half g_w255h[H_];
__device__ float g_x[B_ * C_];
__device__ __half g_actA[B_ * H_];
__device__ __half g_actB[B_ * H_];
__device__ __half g_w16[3][H_ * H_];        // fp16 [N,K] transposed
__device__ __half g_state16[B_ * K0P];      // state fp16, K padded 254->256
__device__ __half g_w0t16[H_ * K0P];        // W0[0:254,:]^T fp16, padded
__device__ float g_part[8 * 16 * 128 * 2];  // [mblock][nblock][row][c]

// ===================== weight transpose to fp16 (all 3 layers, z) ===========
// Fires launch_dependents at start: successor (prep_misc) touches none of w16.
__global__ void wconv_kernel(const float* __restrict__ W1,
                             const float* __restrict__ W2,
                             const float* __restrict__ W3,
                             __half* __restrict__ w16) {
    GDC_LAUNCH();
    __shared__ float t[32][33];
    const float* W = (blockIdx.z == 0) ? W1 : (blockIdx.z == 1) ? W2 : W3;
    __half* dst = w16 + (size_t)blockIdx.z * H_ * H_;
    const int k0 = blockIdx.y * 32, n0 = blockIdx.x * 32;
    const int tx = threadIdx.x, ty = threadIdx.y;
    for (int i = ty; i < 32; i += 8)
        t[i][tx] = W[(size_t)(k0 + i) * H_ + n0 + tx];
    __syncthreads();
    for (int i = ty; i < 32; i += 8)
        dst[(size_t)(n0 + i) * H_ + k0 + tx] = __float2half_rn(t[tx][i]);
}

// ===================== merged small prep (runs concurrent with wconv) =======
// blocks [0,256): W0-head transpose | [256,1280): state conv |
// [1280,1284): w254/w255 | [1284,1484): tvec (4 j-blocks x 50 steps)
__global__ __launch_bounds__(256) void prep_misc(
    const float* __restrict__ W0, const float* __restrict__ state,
    __half* __restrict__ w0t, __half* __restrict__ s16,
    __half* __restrict__ h254, __half* __restrict__ h255,
    __half* __restrict__ tvech)
{
    const int bid = blockIdx.x;
    const int tid = threadIdx.x;
    if (bid < 256) {
        __shared__ float t[32][33];
        const int bx = bid & 31, by = bid >> 5;
        const int k0 = by * 32, n0 = bx * 32;
        const int tx = tid & 31, ty = tid >> 5;
        for (int i = ty; i < 32; i += 8) {
            int k = k0 + i;
            t[i][tx] = (k < S_) ? W0[(size_t)k * H_ + n0 + tx] : 0.0f;
        }
        __syncthreads();
        for (int i = ty; i < 32; i += 8)
            w0t[(size_t)(n0 + i) * K0P + k0 + tx] = __float2half_rn(t[tx][i]);
    } else if (bid < 1280) {
        const int idx = (bid - 256) * 256 + tid;
        const int b = idx >> 8;
        const int k = idx & 255;
        s16[idx] = (k < S_) ? __float2half_rn(state[(size_t)b * S_ + k])
                            : __ushort_as_half((unsigned short)0);
    } else if (bid < 1284) {
        const int j = (bid - 1280) * 256 + tid;
        h254[j] = __float2half_rn(W0[(size_t)254 * H_ + j]);
        h255[j] = __float2half_rn(W0[(size_t)255 * H_ + j]);
    } else {
        __shared__ float temb[64];
        const int q = bid - 1284;
        const int step = q >> 2;
        const int j = (q & 3) * 256 + tid;
        const float tt = (float)step * DT;
        if (tid < 64) {
            int k = tid & 31;
            float freq = expf(-9.210340371976184f * (float)k / 31.0f);
            float ang = tt * freq;
            temb[tid] = (tid < 32) ? sinf(ang) : cosf(ang);
        }
        __syncthreads();
        float acc = 0.0f;
        #pragma unroll
        for (int k = 0; k < 64; k++)
            acc += temb[k] * W0[(size_t)(256 + k) * H_ + j];
        tvech[step * H_ + j] = __float2half_rn(acc);
    }
}

// ===================== fp16 HMMA GEMM common (BK=64, 3 stages) ==============
#define GBM 128
#define GBN 64
#define GBK 64
#define GSTAGES 3
#define OFF_A 0
#define OFF_B 16384
#define STAGE_BYTES 24576
#define GSMEM_TOTAL (GSTAGES * STAGE_BYTES)

__device__ __forceinline__ uint32_t soff(int r, int ch) {
    return (uint32_t)(r * 128 + (((ch ^ r) & 7) << 4));
}

// Parametrized: LDA_ = K-stride of A and W; NKT_ = K / 64.
// Weights (B) prefetched BEFORE griddepcontrol.wait; A after.
// launch_dependents fires AFTER the mainloop (validated placement).
#define GEMM_MAINLOOP(A_, W_, LDA_, NKT_)                                               \
    auto load_A = [&](int kt) {                                                         \
        const uint32_t sb = sbase + (uint32_t)(kt % GSTAGES) * STAGE_BYTES;             \
        const int kb = kt * GBK;                                                        \
        _Pragma("unroll")                                                               \
        for (int i = 0; i < 4; i++) {                                                   \
            int c = tid + i * 256;                                                      \
            int r = c >> 3, ch = c & 7;                                                 \
            CP_ASYNC16(sb + OFF_A + soff(r, ch), A_ + (size_t)(row0 + r) * LDA_ + kb + ch * 8); \
        }                                                                               \
    };                                                                                  \
    auto load_B = [&](int kt) {                                                         \
        const uint32_t sb = sbase + (uint32_t)(kt % GSTAGES) * STAGE_BYTES;             \
        const int kb = kt * GBK;                                                        \
        _Pragma("unroll")                                                               \
        for (int i = 0; i < 2; i++) {                                                   \
            int c = tid + i * 256;                                                      \
            int r = c >> 3, ch = c & 7;                                                 \
            CP_ASYNC16(sb + OFF_B + soff(r, ch), W_ + (size_t)(col0 + r) * LDA_ + kb + ch * 8); \
        }                                                                               \
    };                                                                                  \
    const int a_r = wm * 32 + (lane & 15);                                              \
    const int a_half = lane >> 4;                                                       \
    const int b_r = wn * 32 + (lane & 7) + ((lane >> 4) << 3);                          \
    const int b_half = (lane >> 3) & 1;                                                 \
    load_B(0); load_B(1);          /* weights: independent of predecessor */            \
    GDC_WAIT();                    /* block until predecessor grid flushed */           \
    load_A(0); CP_COMMIT();        /* group0 = B0,B1,A0 */                              \
    load_A(1); CP_COMMIT();        /* group1 = A1 */                                    \
    uint32_t af[2][2][4];                                                               \
    uint32_t bf[2][2][4];                                                               \
    const int NKT = (NKT_);                                                             \
    for (int kt = 0; kt < NKT; kt++) {                                                  \
        CP_WAIT1();                                                                     \
        __syncthreads();                                                                \
        const uint32_t sb = sbase + (uint32_t)(kt % GSTAGES) * STAGE_BYTES;             \
        _Pragma("unroll")                                                               \
        for (int mi = 0; mi < 2; mi++)                                                  \
            ldsm4(af[0][mi], sb + OFF_A + soff(a_r + mi * 16, a_half));                 \
        _Pragma("unroll")                                                               \
        for (int nt = 0; nt < 2; nt++)                                                  \
            ldsm4(bf[0][nt], sb + OFF_B + soff(b_r + nt * 16, b_half));                 \
        _Pragma("unroll")                                                               \
        for (int ks = 0; ks < 4; ks++) {                                                \
            const int cur = ks & 1, nxt = cur ^ 1;                                      \
            if (ks < 3) {                                                               \
                const int ch = (ks + 1) * 2;                                            \
                _Pragma("unroll")                                                       \
                for (int mi = 0; mi < 2; mi++)                                          \
                    ldsm4(af[nxt][mi], sb + OFF_A + soff(a_r + mi * 16, ch + a_half));  \
                _Pragma("unroll")                                                       \
                for (int nt = 0; nt < 2; nt++)                                          \
                    ldsm4(bf[nxt][nt], sb + OFF_B + soff(b_r + nt * 16, ch + b_half));  \
            }                                                                           \
            if (ks == 0) {                                                              \
                if (kt + 2 < NKT) { load_A(kt + 2); load_B(kt + 2); }                   \
                CP_COMMIT();                                                            \
            }                                                                           \
            _Pragma("unroll")                                                           \
            for (int mi = 0; mi < 2; mi++)                                              \
                _Pragma("unroll")                                                       \
                for (int ni = 0; ni < 4; ni++)                                          \
                    mma16816h(acc[mi][ni], af[cur][mi], &bf[cur][ni >> 1][(ni & 1) * 2]); \
        }                                                                               \
    }                                                                                   \
    GDC_LAUNCH();   /* co-residency window = epilogue only */

// ---- variant 1: silu + fp16 store (layers 1, 2) ----
__global__ __launch_bounds__(256, 1) void gemm_hmma(
    const __half* __restrict__ A, const __half* __restrict__ W,
    const float* __restrict__ bias, __half* __restrict__ outC)
{
    extern __shared__ __align__(1024) char gs[];
    const uint32_t sbase = smem_to_u32(gs);
    const int tid = threadIdx.x;
    const int row0 = blockIdx.y * GBM;
    const int col0 = blockIdx.x * GBN;
    const int lane = tid & 31;
    const int wid = tid >> 5;
    const int wm = wid & 3;
    const int wn = wid >> 2;

    float acc[2][4][4];
    #pragma unroll
    for (int mi = 0; mi < 2; mi++)
        #pragma unroll
        for (int ni = 0; ni < 4; ni++)
            #pragma unroll
            for (int q = 0; q < 4; q++) acc[mi][ni][q] = 0.0f;

    GEMM_MAINLOOP(A, W, H_, 16)

    #pragma unroll
    for (int mi = 0; mi < 2; mi++) {
        const int r0g = row0 + wm * 32 + mi * 16 + (lane >> 2);
        #pragma unroll
        for (int ni = 0; ni < 4; ni++) {
            const int cg = col0 + wn * 32 + ni * 8 + (lane & 3) * 2;
            float2 bb = *reinterpret_cast<const float2*>(bias + cg);
            __half2 p0 = __floats2half2_rn(silu_f(acc[mi][ni][0] + bb.x),
                                           silu_f(acc[mi][ni][1] + bb.y));
            __half2 p1 = __floats2half2_rn(silu_f(acc[mi][ni][2] + bb.x),
                                           silu_f(acc[mi][ni][3] + bb.y));
            *reinterpret_cast<__half2*>(outC + (size_t)r0g * H_ + cg) = p0;
            *reinterpret_cast<__half2*>(outC + (size_t)(r0g + 8) * H_ + cg) = p1;
        }
    }
}

// ---- variant 2: layer 3 — silu then fold output head, write partials ----
__global__ __launch_bounds__(256, 1) void gemm_hmma_last(
    const __half* __restrict__ A, const __half* __restrict__ W,
    const float* __restrict__ bias, const float* __restrict__ W4,
    float* __restrict__ part)
{
    extern __shared__ __align__(1024) char gs[];
    __shared__ float spart[128 * 2];
    const uint32_t sbase = smem_to_u32(gs);
    const int tid = threadIdx.x;
    const int row0 = blockIdx.y * GBM;
    const int col0 = blockIdx.x * GBN;
    const int lane = tid & 31;
    const int wid = tid >> 5;
    const int wm = wid & 3;
    const int wn = wid >> 2;

    float acc[2][4][4];
    #pragma unroll
    for (int mi = 0; mi < 2; mi++)
        #pragma unroll
        for (int ni = 0; ni < 4; ni++)
            #pragma unroll
            for (int q = 0; q < 4; q++) acc[mi][ni][q] = 0.0f;

    GEMM_MAINLOOP(A, W, H_, 16)

    const float2* w4 = reinterpret_cast<const float2*>(W4);
    float sum[2][2][2];  // [mi][rhalf][c]
    #pragma unroll
    for (int mi = 0; mi < 2; mi++)
        #pragma unroll
        for (int rh = 0; rh < 2; rh++) { sum[mi][rh][0] = 0.0f; sum[mi][rh][1] = 0.0f; }

    #pragma unroll
    for (int mi = 0; mi < 2; mi++) {
        #pragma unroll
        for (int ni = 0; ni < 4; ni++) {
            const int cg = col0 + wn * 32 + ni * 8 + (lane & 3) * 2;
            float2 bb = *reinterpret_cast<const float2*>(bias + cg);
            float2 w0 = w4[cg], w1 = w4[cg + 1];
            float h00 = silu_f(acc[mi][ni][0] + bb.x);
            float h01 = silu_f(acc[mi][ni][1] + bb.y);
            float h10 = silu_f(acc[mi][ni][2] + bb.x);
            float h11 = silu_f(acc[mi][ni][3] + bb.y);
            sum[mi][0][0] += h00 * w0.x + h01 * w1.x;
            sum[mi][0][1] += h00 * w0.y + h01 * w1.y;
            sum[mi][1][0] += h10 * w0.x + h11 * w1.x;
            sum[mi][1][1] += h10 * w0.y + h11 * w1.y;
        }
    }
    #pragma unroll
    for (int mi = 0; mi < 2; mi++)
        #pragma unroll
        for (int rh = 0; rh < 2; rh++)
            #pragma unroll
            for (int c = 0; c < 2; c++) {
                float v = sum[mi][rh][c];
                v += __shfl_xor_sync(0xffffffffu, v, 1);
                v += __shfl_xor_sync(0xffffffffu, v, 2);
                sum[mi][rh][c] = v;
            }
    if (wn == 0 && (lane & 3) == 0) {
        #pragma unroll
        for (int mi = 0; mi < 2; mi++)
            #pragma unroll
            for (int rh = 0; rh < 2; rh++) {
                int r = wm * 32 + mi * 16 + rh * 8 + (lane >> 2);
                spart[r * 2 + 0] = sum[mi][rh][0];
                spart[r * 2 + 1] = sum[mi][rh][1];
            }
    }
    __syncthreads();
    if (wn == 1 && (lane & 3) == 0) {
        #pragma unroll
        for (int mi = 0; mi < 2; mi++)
            #pragma unroll
            for (int rh = 0; rh < 2; rh++) {
                int r = wm * 32 + mi * 16 + rh * 8 + (lane >> 2);
                spart[r * 2 + 0] += sum[mi][rh][0];
                spart[r * 2 + 1] += sum[mi][rh][1];
            }
    }
    __syncthreads();
    float* dst = part + ((size_t)(blockIdx.y * 16 + blockIdx.x) * 256);
    if (tid < 256) dst[tid] = spart[tid];
}

// ---- variant 3: base0 GEMM (K=256, bias only, fp16 out) --------------------
__global__ __launch_bounds__(256, 1) void gemm_base0(
    const __half* __restrict__ A, const __half* __restrict__ W,
    const float* __restrict__ bias, __half* __restrict__ outC)
{
    extern __shared__ __align__(1024) char gs[];
    const uint32_t sbase = smem_to_u32(gs);
    const int tid = threadIdx.x;
    const int row0 = blockIdx.y * GBM;
    const int col0 = blockIdx.x * GBN;
    const int lane = tid & 31;
    const int wid = tid >> 5;
    const int wm = wid & 3;
    const int wn = wid >> 2;

    float acc[2][4][4];
    #pragma unroll
    for (int mi = 0; mi < 2; mi++)
        #pragma unroll
        for (int ni = 0; ni < 4; ni++)
            #pragma unroll
            for (int q = 0; q < 4; q++) acc[mi][ni][q] = 0.0f;

    GEMM_MAINLOOP(A, W, K0P, 4)

    #pragma unroll
    for (int mi = 0; mi < 2; mi++) {
        const int r0g = row0 + wm * 32 + mi * 16 + (lane >> 2);
        #pragma unroll
        for (int ni = 0; ni < 4; ni++) {
            const int cg = col0 + wn * 32 + ni * 8 + (lane & 3) * 2;
            float2 bb = *reinterpret_cast<const float2*>(bias + cg);
            __half2 p0 = __floats2half2_rn(acc[mi][ni][0] + bb.x, acc[mi][ni][1] + bb.y);
            __half2 p1 = __floats2half2_rn(acc[mi][ni][2] + bb.x, acc[mi][ni][3] + bb.y);
            *reinterpret_cast<__half2*>(outC + (size_t)r0g * H_ + cg) = p0;
            *reinterpret_cast<__half2*>(outC + (size_t)(r0g + 8) * H_ + cg) = p1;
        }
    }
}

// ===================== quarter-row layer0 body (all-fp16 inputs) ============
__device__ __forceinline__ void layer0_quarter(
    const __half* __restrict__ base0h, const __half* __restrict__ tvech,
    const __half* __restrict__ h254, const __half* __restrict__ h255,
    int row, int g, float xb0, float xb1, __half* __restrict__ hOut)
{
    const uint4* bsrc = reinterpret_cast<const uint4*>(base0h + (size_t)row * H_);
    const uint4* tsrc = reinterpret_cast<const uint4*>(tvech);
    const uint4* asrc = reinterpret_cast<const uint4*>(h254);
    const uint4* csrc = reinterpret_cast<const uint4*>(h255);
    uint4 bh = bsrc[g], th = tsrc[g], ah = asrc[g], ch = csrc[g];
    uint4 o;
    const uint32_t* bw = &bh.x;
    const uint32_t* tw = &th.x;
    const uint32_t* aw = &ah.x;
    const uint32_t* cw = &ch.x;
    uint32_t* ow = &o.x;
    #pragma unroll
    for (int w = 0; w < 4; w++) {
        float2 b = __half22float2(*reinterpret_cast<const __half2*>(&bw[w]));
        float2 t = __half22float2(*reinterpret_cast<const __half2*>(&tw[w]));
        float2 a = __half22float2(*reinterpret_cast<const __half2*>(&aw[w]));
        float2 c = __half22float2(*reinterpret_cast<const __half2*>(&cw[w]));
        float v0 = silu_f(b.x + t.x + xb0 * a.x + xb1 * c.x);
        float v1 = silu_f(b.y + t.y + xb0 * a.y + xb1 * c.y);
        *reinterpret_cast<__half2*>(&ow[w]) = __floats2half2_rn(v0, v1);
    }
    reinterpret_cast<uint4*>(hOut + (size_t)row * H_)[g] = o;
}

// ===================== layer-0 activation (step 0 only) =====================
__global__ __launch_bounds__(256) void layer0_act(
    const __half* __restrict__ base0h, const __half* __restrict__ tvec_step,
    const __half* __restrict__ h254, const __half* __restrict__ h255,
    const float* __restrict__ x, __half* __restrict__ h)
{
    const int tid = threadIdx.x;
    const int lane = tid & 31;
    const int wid = tid >> 5;
    const int row = blockIdx.x * 2 + (wid >> 2);
    const float xv0 = x[2 * row];
    const float xv1 = x[2 * row + 1];
    const int g = (wid & 3) * 32 + lane;
    layer0_quarter(base0h, tvec_step, h254, h255, row, g, xv0, xv1, h);
}

// ===================== fused: partial-sum + Euler + next-step layer0 ========
__global__ __launch_bounds__(256) void step_fuse(
    const float* __restrict__ part,
    const float* __restrict__ b4,
    float* __restrict__ x,
    const __half* __restrict__ base0h, const __half* __restrict__ tvec_next,
    const __half* __restrict__ h254, const __half* __restrict__ h255,
    __half* __restrict__ hOut)
{
    GDC_WAIT();
    GDC_LAUNCH();
    const int tid = threadIdx.x;
    const int lane = tid & 31;
    const int wid = tid >> 5;
    const int rbase = blockIdx.x * 2;

    __shared__ float sx[2][2];

    if (wid < 2) {
        const int row = rbase + wid;
        const int by = row >> 7, rl = row & 127;
        float v0 = 0.0f, v1 = 0.0f;
        if (lane < 16) {
            float2 p = *reinterpret_cast<const float2*>(
                part + ((size_t)(by * 16 + lane) * 128 + rl) * 2);
            v0 = p.x; v1 = p.y;
        }
        #pragma unroll
        for (int o = 8; o > 0; o >>= 1) {
            v0 += __shfl_down_sync(0xffffffffu, v0, o);
            v1 += __shfl_down_sync(0xffffffffu, v1, o);
        }
        if (lane == 0) {
            v0 = x[2 * row]     + DT * (v0 + b4[0]);
            v1 = x[2 * row + 1] + DT * (v1 + b4[1]);
            x[2 * row] = v0; x[2 * row + 1] = v1;
            sx[wid][0] = v0; sx[wid][1] = v1;
        }
    }
    __syncthreads();

    const int rl = wid >> 2;
    const int row = rbase + rl;
    const float xv0 = sx[rl][0];
    const float xv1 = sx[rl][1];
    const int g = (wid & 3) * 32 + lane;
    layer0_quarter(base0h, tvec_next, h254, h255, row, g, xv0, xv1, hOut);
}

// ===================== final: partial-sum + Euler -> out ====================
__global__ __launch_bounds__(256) void out_euler(
    const float* __restrict__ part,
    const float* __restrict__ b4,
    const float* __restrict__ x, float* __restrict__ out)
{
    GDC_WAIT();
    const int tid = threadIdx.x;
    const int lane = tid & 31;
    const int wid = tid >> 5;
    const int row = blockIdx.x * 8 + wid;
    const int by = row >> 7, rl = row & 127;
    float v0 = 0.0f, v1 = 0.0f;
    if (lane < 16) {
        float2 p = *reinterpret_cast<const float2*>(
            part + ((size_t)(by * 16 + lane) * 128 + rl) * 2);
        v0 = p.x; v1 = p.y;
    }
    #pragma unroll
    for (int o = 8; o > 0; o >>= 1) {
        v0 += __shfl_down_sync(0xffffffffu, v0, o);
        v1 += __shfl_down_sync(0xffffffffu, v1, o);
    }
    if (lane == 0) {
        out[2 * row]     = x[2 * row]     + DT * (v0 + b4[0]);
        out[2 * row + 1] = x[2 * row + 1] + DT * (v1 + b4[1]);
    }
}

// ===================== host side ============================================
template <typename KernelT, typename... Args>
static void launch_pdl(KernelT k, dim3 g, dim3 b, size_t smem, Args... args) {
    cudaLaunchConfig_t cfg = {};
    cfg.gridDim = g;
    cfg.blockDim = b;
    cfg.dynamicSmemBytes = smem;
    cfg.stream = 0;
    cudaLaunchAttribute at[1];
    at[0].id = cudaLaunchAttributeProgrammaticStreamSerialization;
    at[0].val.programmaticStreamSerializationAllowed = 1;
    cfg.attrs = at;
    cfg.numAttrs = 1;
    cudaLaunchKernelEx(&cfg, k, args...);
}

extern "C" void kernel_launch(void* const* d_in, const int* in_sizes, int n_in,
                              void* d_out, int out_size)
{
    const float* state = (const float*)d_in[0];
    const float* x0    = (const float*)d_in[1];
    const float* W0    = (const float*)d_in[2];
    const float* b0    = (const float*)d_in[3];
    const float* W1    = (const float*)d_in[4];
    const float* b1    = (const float*)d_in[5];
    const float* W2    = (const float*)d_in[6];
    const float* b2    = (const float*)d_in[7];
    const float* W3    = (const float*)d_in[8];
    const float* b3    = (const float*)d_in[9];
    const float* W4    = (const float*)d_in[10];
    const float* b4    = (const float*)d_in[11];
    float* out = (float*)d_out;

    float *xp, *partp;
    __half *base0h, *tvech, *h254, *h255, *actA, *actB, *w16, *s16, *w0t;
    cudaGetSymbolAddress((void**)&base0h, g_base0h);
    cudaGetSymbolAddress((void**)&tvech,  g_tvech);
    cudaGetSymbolAddress((void**)&h254,   g_w254h);
    cudaGetSymbolAddress((void**)&h255,   g_w255h);
    cudaGetSymbolAddress((void**)&xp,     g_x);
    cudaGetSymbolAddress((void**)&actA,   g_actA);
    cudaGetSymbolAddress((void**)&actB,   g_actB);
    cudaGetSymbolAddress((void**)&w16,    g_w16);
    cudaGetSymbolAddress((void**)&s16,    g_state16);
    cudaGetSymbolAddress((void**)&w0t,    g_w0t16);
    cudaGetSymbolAddress((void**)&partp,  g_part);

    static bool attr_set = false;
    if (!attr_set) {
        cudaFuncSetAttribute(gemm_hmma, cudaFuncAttributeMaxDynamicSharedMemorySize,
                             GSMEM_TOTAL);
        cudaFuncSetAttribute(gemm_hmma_last, cudaFuncAttributeMaxDynamicSharedMemorySize,
                             GSMEM_TOTAL);
        cudaFuncSetAttribute(gemm_base0, cudaFuncAttributeMaxDynamicSharedMemorySize,
                             GSMEM_TOTAL);
        attr_set = true;
    }

    // one-time prep: wconv fires launch_dependents at start; prep_misc (PDL)
    // overlaps it. gemm_base0 / layer0_act are normal launches = full barriers.
    cudaMemcpyAsync(xp, x0, B_ * C_ * sizeof(float), cudaMemcpyDeviceToDevice);
    wconv_kernel<<<dim3(32, 32, 3), dim3(32, 8)>>>(W1, W2, W3, w16);
    launch_pdl(prep_misc, dim3(1484), dim3(256), (size_t)0,
               W0, state, w0t, s16, h254, h255, tvech);

    dim3 ggrid(H_ / GBN, B_ / GBM);  // (16, 8) = 128 CTAs
    gemm_base0<<<ggrid, 256, GSMEM_TOTAL>>>(s16, w0t, b0, base0h);

    __half* wl0 = w16 + 0 * (size_t)H_ * H_;
    __half* wl1 = w16 + 1 * (size_t)H_ * H_;
    __half* wl2 = w16 + 2 * (size_t)H_ * H_;

    layer0_act<<<B_ / 2, 256>>>(base0h, tvech, h254, h255, xp, actA);
    for (int i = 0; i < NSTEPS; i++) {
        launch_pdl(gemm_hmma, ggrid, dim3(256), (size_t)GSMEM_TOTAL,
                   (const __half*)actA, (const __half*)wl0, b1, actB);
        launch_pdl(gemm_hmma, ggrid, dim3(256), (size_t)GSMEM_TOTAL,
                   (const __half*)actB, (const __half*)wl1, b2, actA);
        launch_pdl(gemm_hmma_last, ggrid, dim3(256), (size_t)GSMEM_TOTAL,
                   (const __half*)actA, (const __half*)wl2, b3, W4, partp);
        if (i + 1 < NSTEPS) {
            launch_pdl(step_fuse, dim3(B_ / 2), dim3(256), (size_t)0,
                       (const float*)partp, b4, xp, (const __half*)base0h,
                       (const __half*)(tvech + (size_t)(i + 1) * H_), h254, h255, actA);
        } else {
            launch_pdl(out_euler, dim3(B_ / 8), dim3(256), (size_t)0,
                       (const float*)partp, b4, (const float*)xp, out);
        }
    }
}

// round 17
// speedup vs baseline: 1.0274x; 1.0064x over previous
#include <cuda_runtime.h>
#include <cuda_fp16.h>
#include <math.h>
#include <stdint.h>

#define B_ 1024
#define S_ 254
#define C_ 2
#define H_ 1024
#define K0P 256
#define NSTEPS 50
#define DT 0.02f

// ===================== helpers =============================================
__device__ __forceinline__ uint32_t smem_to_u32(const void* p) {
    uint32_t a;
    asm("{ .reg .u64 t; cvta.to.shared.u64 t, %1; cvt.u32.u64 %0, t; }" : "=r"(a) : "l"(p));
    return a;
}
#define CP_ASYNC16(dst, src) \
    asm volatile("cp.async.cg.shared.global [%0], [%1], 16;" :: "r"(dst), "l"(src) : "memory")
#define CP_COMMIT() asm volatile("cp.async.commit_group;" ::: "memory")
#define CP_WAIT1() asm volatile("cp.async.wait_group 1;" ::: "memory")

// PDL
#define GDC_WAIT()   asm volatile("griddepcontrol.wait;" ::: "memory")
#define GDC_LAUNCH() asm volatile("griddepcontrol.launch_dependents;" ::: "memory")

__device__ __forceinline__ void ldsm4(uint32_t* r, uint32_t addr) {
    asm volatile("ldmatrix.sync.aligned.m8n8.x4.shared.b16 {%0,%1,%2,%3}, [%4];"
        : "=r"(r[0]), "=r"(r[1]), "=r"(r[2]), "=r"(r[3]) : "r"(addr));
}
__device__ __forceinline__ void mma16816h(float* c, const uint32_t* a, const uint32_t* b) {
    asm volatile("mma.sync.aligned.m16n8k16.row.col.f32.f16.f16.f32 "
        "{%0,%1,%2,%3}, {%4,%5,%6,%7}, {%8,%9}, {%0,%1,%2,%3};"
        : "+f"(c[0]), "+f"(c[1]), "+f"(c[2]), "+f"(c[3])
        : "r"(a[0]), "r"(a[1]), "r"(a[2]), "r"(a[3]), "r"(b[0]), "r"(b[1]));
}

__device__ __forceinline__ float silu_f(float v) { return v / (1.0f + __expf(-v)); }

// ===================== scratch (device globals, no allocs) ==================
__device__ __half g_base0h[B_ * H_];
__device__ __half g_tvech[NSTEPS * H_];
__device__ __half g_w254h[H_];
__device__ __half g_w255h[H_];
__device__ float g_x[B_ * C_];
__device__ __half g_actA[B_ * H_];
__device__ __half g_actB[B_ * H_];
__device__ __half g_w16[3][H_ * H_];        // fp16 [N,K] transposed
__device__ __half g_state16[B_ * K0P];      // state fp16, K padded 254->256
__device__ __half g_w0t16[H_ * K0P];        // W0[0:254,:]^T fp16, padded
__device__ float g_part[8 * 16 * 128 * 2];  // [mblock][nblock][row][c]

// ===================== weight transpose to fp16 (all 3 layers, z) ===========
__global__ void wconv_kernel(const float* __restrict__ W1,
                             const float* __restrict__ W2,
                             const float* __restrict__ W3,
                             __half* __restrict__ w16) {
    GDC_LAUNCH();
    __shared__ float t[32][33];
    const float* W = (blockIdx.z == 0) ? W1 : (blockIdx.z == 1) ? W2 : W3;
    __half* dst = w16 + (size_t)blockIdx.z * H_ * H_;
    const int k0 = blockIdx.y * 32, n0 = blockIdx.x * 32;
    const int tx = threadIdx.x, ty = threadIdx.y;
    for (int i = ty; i < 32; i += 8)
        t[i][tx] = W[(size_t)(k0 + i) * H_ + n0 + tx];
    __syncthreads();
    for (int i = ty; i < 32; i += 8)
        dst[(size_t)(n0 + i) * H_ + k0 + tx] = __float2half_rn(t[tx][i]);
}

// ===================== merged small prep (runs concurrent with wconv) =======
__global__ __launch_bounds__(256) void prep_misc(
    const float* __restrict__ W0, const float* __restrict__ state,
    __half* __restrict__ w0t, __half* __restrict__ s16,
    __half* __restrict__ h254, __half* __restrict__ h255,
    __half* __restrict__ tvech)
{
    const int bid = blockIdx.x;
    const int tid = threadIdx.x;
    if (bid < 256) {
        __shared__ float t[32][33];
        const int bx = bid & 31, by = bid >> 5;
        const int k0 = by * 32, n0 = bx * 32;
        const int tx = tid & 31, ty = tid >> 5;
        for (int i = ty; i < 32; i += 8) {
            int k = k0 + i;
            t[i][tx] = (k < S_) ? W0[(size_t)k * H_ + n0 + tx] : 0.0f;
        }
        __syncthreads();
        for (int i = ty; i < 32; i += 8)
            w0t[(size_t)(n0 + i) * K0P + k0 + tx] = __float2half_rn(t[tx][i]);
    } else if (bid < 1280) {
        const int idx = (bid - 256) * 256 + tid;
        const int b = idx >> 8;
        const int k = idx & 255;
        s16[idx] = (k < S_) ? __float2half_rn(state[(size_t)b * S_ + k])
                            : __ushort_as_half((unsigned short)0);
    } else if (bid < 1284) {
        const int j = (bid - 1280) * 256 + tid;
        h254[j] = __float2half_rn(W0[(size_t)254 * H_ + j]);
        h255[j] = __float2half_rn(W0[(size_t)255 * H_ + j]);
    } else {
        __shared__ float temb[64];
        const int q = bid - 1284;
        const int step = q >> 2;
        const int j = (q & 3) * 256 + tid;
        const float tt = (float)step * DT;
        if (tid < 64) {
            int k = tid & 31;
            float freq = expf(-9.210340371976184f * (float)k / 31.0f);
            float ang = tt * freq;
            temb[tid] = (tid < 32) ? sinf(ang) : cosf(ang);
        }
        __syncthreads();
        float acc = 0.0f;
        #pragma unroll
        for (int k = 0; k < 64; k++)
            acc += temb[k] * W0[(size_t)(256 + k) * H_ + j];
        tvech[step * H_ + j] = __float2half_rn(acc);
    }
}

// ===================== fp16 HMMA GEMM common (BK=64, 3 stages) ==============
#define GBM 128
#define GBN 64
#define GBK 64
#define GSTAGES 3
#define OFF_A 0
#define OFF_B 16384
#define STAGE_BYTES 24576
#define GSMEM_TOTAL (GSTAGES * STAGE_BYTES)

__device__ __forceinline__ uint32_t soff(int r, int ch) {
    return (uint32_t)(r * 128 + (((ch ^ r) & 7) << 4));
}

#define GEMM_MAINLOOP(A_, W_, LDA_, NKT_)                                               \
    auto load_A = [&](int kt) {                                                         \
        const uint32_t sb = sbase + (uint32_t)(kt % GSTAGES) * STAGE_BYTES;             \
        const int kb = kt * GBK;                                                        \
        _Pragma("unroll")                                                               \
        for (int i = 0; i < 4; i++) {                                                   \
            int c = tid + i * 256;                                                      \
            int r = c >> 3, ch = c & 7;                                                 \
            CP_ASYNC16(sb + OFF_A + soff(r, ch), A_ + (size_t)(row0 + r) * LDA_ + kb + ch * 8); \
        }                                                                               \
    };                                                                                  \
    auto load_B = [&](int kt) {                                                         \
        const uint32_t sb = sbase + (uint32_t)(kt % GSTAGES) * STAGE_BYTES;             \
        const int kb = kt * GBK;                                                        \
        _Pragma("unroll")                                                               \
        for (int i = 0; i < 2; i++) {                                                   \
            int c = tid + i * 256;                                                      \
            int r = c >> 3, ch = c & 7;                                                 \
            CP_ASYNC16(sb + OFF_B + soff(r, ch), W_ + (size_t)(col0 + r) * LDA_ + kb + ch * 8); \
        }                                                                               \
    };                                                                                  \
    const int a_r = wm * 32 + (lane & 15);                                              \
    const int a_half = lane >> 4;                                                       \
    const int b_r = wn * 32 + (lane & 7) + ((lane >> 4) << 3);                          \
    const int b_half = (lane >> 3) & 1;                                                 \
    load_B(0); load_B(1);          /* weights: independent of predecessor */            \
    GDC_WAIT();                    /* block until predecessor grid flushed */           \
    load_A(0); CP_COMMIT();        /* group0 = B0,B1,A0 */                              \
    load_A(1); CP_COMMIT();        /* group1 = A1 */                                    \
    uint32_t af[2][2][4];                                                               \
    uint32_t bf[2][2][4];                                                               \
    const int NKT = (NKT_);                                                             \
    for (int kt = 0; kt < NKT; kt++) {                                                  \
        CP_WAIT1();                                                                     \
        __syncthreads();                                                                \
        const uint32_t sb = sbase + (uint32_t)(kt % GSTAGES) * STAGE_BYTES;             \
        _Pragma("unroll")                                                               \
        for (int mi = 0; mi < 2; mi++)                                                  \
            ldsm4(af[0][mi], sb + OFF_A + soff(a_r + mi * 16, a_half));                 \
        _Pragma("unroll")                                                               \
        for (int nt = 0; nt < 2; nt++)                                                  \
            ldsm4(bf[0][nt], sb + OFF_B + soff(b_r + nt * 16, b_half));                 \
        _Pragma("unroll")                                                               \
        for (int ks = 0; ks < 4; ks++) {                                                \
            const int cur = ks & 1, nxt = cur ^ 1;                                      \
            if (ks < 3) {                                                               \
                const int ch = (ks + 1) * 2;                                            \
                _Pragma("unroll")                                                       \
                for (int mi = 0; mi < 2; mi++)                                          \
                    ldsm4(af[nxt][mi], sb + OFF_A + soff(a_r + mi * 16, ch + a_half));  \
                _Pragma("unroll")                                                       \
                for (int nt = 0; nt < 2; nt++)                                          \
                    ldsm4(bf[nxt][nt], sb + OFF_B + soff(b_r + nt * 16, ch + b_half));  \
            }                                                                           \
            if (ks == 0) {                                                              \
                if (kt + 2 < NKT) { load_A(kt + 2); load_B(kt + 2); }                   \
                CP_COMMIT();                                                            \
            }                                                                           \
            _Pragma("unroll")                                                           \
            for (int mi = 0; mi < 2; mi++)                                              \
                _Pragma("unroll")                                                       \
                for (int ni = 0; ni < 4; ni++)                                          \
                    mma16816h(acc[mi][ni], af[cur][mi], &bf[cur][ni >> 1][(ni & 1) * 2]); \
        }                                                                               \
    }                                                                                   \
    GDC_LAUNCH();   /* co-residency window = epilogue only */

// ---- variant 1: silu + fp16 store (layers 1, 2) ----
__global__ __launch_bounds__(256, 1) void gemm_hmma(
    const __half* __restrict__ A, const __half* __restrict__ W,
    const float* __restrict__ bias, __half* __restrict__ outC)
{
    extern __shared__ __align__(1024) char gs[];
    const uint32_t sbase = smem_to_u32(gs);
    const int tid = threadIdx.x;
    const int row0 = blockIdx.y * GBM;
    const int col0 = blockIdx.x * GBN;
    const int lane = tid & 31;
    const int wid = tid >> 5;
    const int wm = wid & 3;
    const int wn = wid >> 2;

    float acc[2][4][4];
    #pragma unroll
    for (int mi = 0; mi < 2; mi++)
        #pragma unroll
        for (int ni = 0; ni < 4; ni++)
            #pragma unroll
            for (int q = 0; q < 4; q++) acc[mi][ni][q] = 0.0f;

    GEMM_MAINLOOP(A, W, H_, 16)

    #pragma unroll
    for (int mi = 0; mi < 2; mi++) {
        const int r0g = row0 + wm * 32 + mi * 16 + (lane >> 2);
        #pragma unroll
        for (int ni = 0; ni < 4; ni++) {
            const int cg = col0 + wn * 32 + ni * 8 + (lane & 3) * 2;
            float2 bb = *reinterpret_cast<const float2*>(bias + cg);
            __half2 p0 = __floats2half2_rn(silu_f(acc[mi][ni][0] + bb.x),
                                           silu_f(acc[mi][ni][1] + bb.y));
            __half2 p1 = __floats2half2_rn(silu_f(acc[mi][ni][2] + bb.x),
                                           silu_f(acc[mi][ni][3] + bb.y));
            *reinterpret_cast<__half2*>(outC + (size_t)r0g * H_ + cg) = p0;
            *reinterpret_cast<__half2*>(outC + (size_t)(r0g + 8) * H_ + cg) = p1;
        }
    }
}

// ---- variant 2: layer 3 — silu then fold output head, write partials ----
__global__ __launch_bounds__(256, 1) void gemm_hmma_last(
    const __half* __restrict__ A, const __half* __restrict__ W,
    const float* __restrict__ bias, const float* __restrict__ W4,
    float* __restrict__ part)
{
    extern __shared__ __align__(1024) char gs[];
    __shared__ float spart[128 * 2];
    const uint32_t sbase = smem_to_u32(gs);
    const int tid = threadIdx.x;
    const int row0 = blockIdx.y * GBM;
    const int col0 = blockIdx.x * GBN;
    const int lane = tid & 31;
    const int wid = tid >> 5;
    const int wm = wid & 3;
    const int wn = wid >> 2;

    float acc[2][4][4];
    #pragma unroll
    for (int mi = 0; mi < 2; mi++)
        #pragma unroll
        for (int ni = 0; ni < 4; ni++)
            #pragma unroll
            for (int q = 0; q < 4; q++) acc[mi][ni][q] = 0.0f;

    GEMM_MAINLOOP(A, W, H_, 16)

    const float2* w4 = reinterpret_cast<const float2*>(W4);
    float sum[2][2][2];  // [mi][rhalf][c]
    #pragma unroll
    for (int mi = 0; mi < 2; mi++)
        #pragma unroll
        for (int rh = 0; rh < 2; rh++) { sum[mi][rh][0] = 0.0f; sum[mi][rh][1] = 0.0f; }

    #pragma unroll
    for (int mi = 0; mi < 2; mi++) {
        #pragma unroll
        for (int ni = 0; ni < 4; ni++) {
            const int cg = col0 + wn * 32 + ni * 8 + (lane & 3) * 2;
            float2 bb = *reinterpret_cast<const float2*>(bias + cg);
            float2 w0 = w4[cg], w1 = w4[cg + 1];
            float h00 = silu_f(acc[mi][ni][0] + bb.x);
            float h01 = silu_f(acc[mi][ni][1] + bb.y);
            float h10 = silu_f(acc[mi][ni][2] + bb.x);
            float h11 = silu_f(acc[mi][ni][3] + bb.y);
            sum[mi][0][0] += h00 * w0.x + h01 * w1.x;
            sum[mi][0][1] += h00 * w0.y + h01 * w1.y;
            sum[mi][1][0] += h10 * w0.x + h11 * w1.x;
            sum[mi][1][1] += h10 * w0.y + h11 * w1.y;
        }
    }
    #pragma unroll
    for (int mi = 0; mi < 2; mi++)
        #pragma unroll
        for (int rh = 0; rh < 2; rh++)
            #pragma unroll
            for (int c = 0; c < 2; c++) {
                float v = sum[mi][rh][c];
                v += __shfl_xor_sync(0xffffffffu, v, 1);
                v += __shfl_xor_sync(0xffffffffu, v, 2);
                sum[mi][rh][c] = v;
            }
    if (wn == 0 && (lane & 3) == 0) {
        #pragma unroll
        for (int mi = 0; mi < 2; mi++)
            #pragma unroll
            for (int rh = 0; rh < 2; rh++) {
                int r = wm * 32 + mi * 16 + rh * 8 + (lane >> 2);
                spart[r * 2 + 0] = sum[mi][rh][0];
                spart[r * 2 + 1] = sum[mi][rh][1];
            }
    }
    __syncthreads();
    if (wn == 1 && (lane & 3) == 0) {
        #pragma unroll
        for (int mi = 0; mi < 2; mi++)
            #pragma unroll
            for (int rh = 0; rh < 2; rh++) {
                int r = wm * 32 + mi * 16 + rh * 8 + (lane >> 2);
                spart[r * 2 + 0] += sum[mi][rh][0];
                spart[r * 2 + 1] += sum[mi][rh][1];
            }
    }
    __syncthreads();
    float* dst = part + ((size_t)(blockIdx.y * 16 + blockIdx.x) * 256);
    if (tid < 256) dst[tid] = spart[tid];
}

// ---- variant 3: base0 GEMM (K=256, bias only, fp16 out) --------------------
__global__ __launch_bounds__(256, 1) void gemm_base0(
    const __half* __restrict__ A, const __half* __restrict__ W,
    const float* __restrict__ bias, __half* __restrict__ outC)
{
    extern __shared__ __align__(1024) char gs[];
    const uint32_t sbase = smem_to_u32(gs);
    const int tid = threadIdx.x;
    const int row0 = blockIdx.y * GBM;
    const int col0 = blockIdx.x * GBN;
    const int lane = tid & 31;
    const int wid = tid >> 5;
    const int wm = wid & 3;
    const int wn = wid >> 2;

    float acc[2][4][4];
    #pragma unroll
    for (int mi = 0; mi < 2; mi++)
        #pragma unroll
        for (int ni = 0; ni < 4; ni++)
            #pragma unroll
            for (int q = 0; q < 4; q++) acc[mi][ni][q] = 0.0f;

    GEMM_MAINLOOP(A, W, K0P, 4)

    #pragma unroll
    for (int mi = 0; mi < 2; mi++) {
        const int r0g = row0 + wm * 32 + mi * 16 + (lane >> 2);
        #pragma unroll
        for (int ni = 0; ni < 4; ni++) {
            const int cg = col0 + wn * 32 + ni * 8 + (lane & 3) * 2;
            float2 bb = *reinterpret_cast<const float2*>(bias + cg);
            __half2 p0 = __floats2half2_rn(acc[mi][ni][0] + bb.x, acc[mi][ni][1] + bb.y);
            __half2 p1 = __floats2half2_rn(acc[mi][ni][2] + bb.x, acc[mi][ni][3] + bb.y);
            *reinterpret_cast<__half2*>(outC + (size_t)r0g * H_ + cg) = p0;
            *reinterpret_cast<__half2*>(outC + (size_t)(r0g + 8) * H_ + cg) = p1;
        }
    }
}

// ===================== layer-0 compute from preloaded registers =============
__device__ __forceinline__ void layer0_compute_store(
    uint4 bh, uint4 th, uint4 ah, uint4 ch,
    float xb0, float xb1, int row, int g, __half* __restrict__ hOut)
{
    uint4 o;
    const uint32_t* bw = &bh.x;
    const uint32_t* tw = &th.x;
    const uint32_t* aw = &ah.x;
    const uint32_t* cw = &ch.x;
    uint32_t* ow = &o.x;
    #pragma unroll
    for (int w = 0; w < 4; w++) {
        float2 b = __half22float2(*reinterpret_cast<const __half2*>(&bw[w]));
        float2 t = __half22float2(*reinterpret_cast<const __half2*>(&tw[w]));
        float2 a = __half22float2(*reinterpret_cast<const __half2*>(&aw[w]));
        float2 c = __half22float2(*reinterpret_cast<const __half2*>(&cw[w]));
        float v0 = silu_f(b.x + t.x + xb0 * a.x + xb1 * c.x);
        float v1 = silu_f(b.y + t.y + xb0 * a.y + xb1 * c.y);
        *reinterpret_cast<__half2*>(&ow[w]) = __floats2half2_rn(v0, v1);
    }
    reinterpret_cast<uint4*>(hOut + (size_t)row * H_)[g] = o;
}

// ===================== layer-0 activation (step 0 only) =====================
__global__ __launch_bounds__(256) void layer0_act(
    const __half* __restrict__ base0h, const __half* __restrict__ tvec_step,
    const __half* __restrict__ h254, const __half* __restrict__ h255,
    const float* __restrict__ x, __half* __restrict__ h)
{
    const int tid = threadIdx.x;
    const int lane = tid & 31;
    const int wid = tid >> 5;
    const int row = blockIdx.x * 2 + (wid >> 2);
    const int g = (wid & 3) * 32 + lane;
    uint4 bh = reinterpret_cast<const uint4*>(base0h + (size_t)row * H_)[g];
    uint4 th = reinterpret_cast<const uint4*>(tvec_step)[g];
    uint4 ah = reinterpret_cast<const uint4*>(h254)[g];
    uint4 ch = reinterpret_cast<const uint4*>(h255)[g];
    const float xv0 = x[2 * row];
    const float xv1 = x[2 * row + 1];
    layer0_compute_store(bh, th, ah, ch, xv0, xv1, row, g, h);
}

// ===================== fused: partial-sum + Euler + next-step layer0 ========
// Layer-0 vector loads issued BEFORE the reduce barrier so they overlap the
// partial-sum latency (compiler cannot hoist loads across __syncthreads).
__global__ __launch_bounds__(256) void step_fuse(
    const float* __restrict__ part,
    const float* __restrict__ b4,
    float* __restrict__ x,
    const __half* __restrict__ base0h, const __half* __restrict__ tvec_next,
    const __half* __restrict__ h254, const __half* __restrict__ h255,
    __half* __restrict__ hOut)
{
    GDC_WAIT();
    GDC_LAUNCH();
    const int tid = threadIdx.x;
    const int lane = tid & 31;
    const int wid = tid >> 5;
    const int rbase = blockIdx.x * 2;

    // ---- prefetch layer-0 inputs (independent of x) ----
    const int rl = wid >> 2;              // row-local 0..1
    const int row_l0 = rbase + rl;
    const int g = (wid & 3) * 32 + lane;
    uint4 bh = reinterpret_cast<const uint4*>(base0h + (size_t)row_l0 * H_)[g];
    uint4 th = reinterpret_cast<const uint4*>(tvec_next)[g];
    uint4 ah = reinterpret_cast<const uint4*>(h254)[g];
    uint4 ch = reinterpret_cast<const uint4*>(h255)[g];

    __shared__ float sx[2][2];

    // ---- partial reduce + Euler (warps 0-1), overlapped with loads above ----
    if (wid < 2) {
        const int row = rbase + wid;
        const int by = row >> 7, rlp = row & 127;
        float v0 = 0.0f, v1 = 0.0f;
        if (lane < 16) {
            float2 p = *reinterpret_cast<const float2*>(
                part + ((size_t)(by * 16 + lane) * 128 + rlp) * 2);
            v0 = p.x; v1 = p.y;
        }
        #pragma unroll
        for (int o = 8; o > 0; o >>= 1) {
            v0 += __shfl_down_sync(0xffffffffu, v0, o);
            v1 += __shfl_down_sync(0xffffffffu, v1, o);
        }
        if (lane == 0) {
            v0 = x[2 * row]     + DT * (v0 + b4[0]);
            v1 = x[2 * row + 1] + DT * (v1 + b4[1]);
            x[2 * row] = v0; x[2 * row + 1] = v1;
            sx[wid][0] = v0; sx[wid][1] = v1;
        }
    }
    __syncthreads();

    const float xv0 = sx[rl][0];
    const float xv1 = sx[rl][1];
    layer0_compute_store(bh, th, ah, ch, xv0, xv1, row_l0, g, hOut);
}

// ===================== final: partial-sum + Euler -> out ====================
__global__ __launch_bounds__(256) void out_euler(
    const float* __restrict__ part,
    const float* __restrict__ b4,
    const float* __restrict__ x, float* __restrict__ out)
{
    GDC_WAIT();
    const int tid = threadIdx.x;
    const int lane = tid & 31;
    const int wid = tid >> 5;
    const int row = blockIdx.x * 8 + wid;
    const int by = row >> 7, rl = row & 127;
    float v0 = 0.0f, v1 = 0.0f;
    if (lane < 16) {
        float2 p = *reinterpret_cast<const float2*>(
            part + ((size_t)(by * 16 + lane) * 128 + rl) * 2);
        v0 = p.x; v1 = p.y;
    }
    #pragma unroll
    for (int o = 8; o > 0; o >>= 1) {
        v0 += __shfl_down_sync(0xffffffffu, v0, o);
        v1 += __shfl_down_sync(0xffffffffu, v1, o);
    }
    if (lane == 0) {
        out[2 * row]     = x[2 * row]     + DT * (v0 + b4[0]);
        out[2 * row + 1] = x[2 * row + 1] + DT * (v1 + b4[1]);
    }
}

// ===================== host side ============================================
template <typename KernelT, typename... Args>
static void launch_pdl(KernelT k, dim3 g, dim3 b, size_t smem, Args... args) {
    cudaLaunchConfig_t cfg = {};
    cfg.gridDim = g;
    cfg.blockDim = b;
    cfg.dynamicSmemBytes = smem;
    cfg.stream = 0;
    cudaLaunchAttribute at[1];
    at[0].id = cudaLaunchAttributeProgrammaticStreamSerialization;
    at[0].val.programmaticStreamSerializationAllowed = 1;
    cfg.attrs = at;
    cfg.numAttrs = 1;
    cudaLaunchKernelEx(&cfg, k, args...);
}

extern "C" void kernel_launch(void* const* d_in, const int* in_sizes, int n_in,
                              void* d_out, int out_size)
{
    const float* state = (const float*)d_in[0];
    const float* x0    = (const float*)d_in[1];
    const float* W0    = (const float*)d_in[2];
    const float* b0    = (const float*)d_in[3];
    const float* W1    = (const float*)d_in[4];
    const float* b1    = (const float*)d_in[5];
    const float* W2    = (const float*)d_in[6];
    const float* b2    = (const float*)d_in[7];
    const float* W3    = (const float*)d_in[8];
    const float* b3    = (const float*)d_in[9];
    const float* W4    = (const float*)d_in[10];
    const float* b4    = (const float*)d_in[11];
    float* out = (float*)d_out;

    float *xp, *partp;
    __half *base0h, *tvech, *h254, *h255, *actA, *actB, *w16, *s16, *w0t;
    cudaGetSymbolAddress((void**)&base0h, g_base0h);
    cudaGetSymbolAddress((void**)&tvech,  g_tvech);
    cudaGetSymbolAddress((void**)&h254,   g_w254h);
    cudaGetSymbolAddress((void**)&h255,   g_w255h);
    cudaGetSymbolAddress((void**)&xp,     g_x);
    cudaGetSymbolAddress((void**)&actA,   g_actA);
    cudaGetSymbolAddress((void**)&actB,   g_actB);
    cudaGetSymbolAddress((void**)&w16,    g_w16);
    cudaGetSymbolAddress((void**)&s16,    g_state16);
    cudaGetSymbolAddress((void**)&w0t,    g_w0t16);
    cudaGetSymbolAddress((void**)&partp,  g_part);

    static bool attr_set = false;
    if (!attr_set) {
        cudaFuncSetAttribute(gemm_hmma, cudaFuncAttributeMaxDynamicSharedMemorySize,
                             GSMEM_TOTAL);
        cudaFuncSetAttribute(gemm_hmma_last, cudaFuncAttributeMaxDynamicSharedMemorySize,
                             GSMEM_TOTAL);
        cudaFuncSetAttribute(gemm_base0, cudaFuncAttributeMaxDynamicSharedMemorySize,
                             GSMEM_TOTAL);
        attr_set = true;
    }

    // one-time prep: wconv fires launch_dependents at start; prep_misc (PDL)
    // overlaps it. gemm_base0 / layer0_act are normal launches = full barriers.
    cudaMemcpyAsync(xp, x0, B_ * C_ * sizeof(float), cudaMemcpyDeviceToDevice);
    wconv_kernel<<<dim3(32, 32, 3), dim3(32, 8)>>>(W1, W2, W3, w16);
    launch_pdl(prep_misc, dim3(1484), dim3(256), (size_t)0,
               W0, state, w0t, s16, h254, h255, tvech);

    dim3 ggrid(H_ / GBN, B_ / GBM);  // (16, 8) = 128 CTAs
    gemm_base0<<<ggrid, 256, GSMEM_TOTAL>>>(s16, w0t, b0, base0h);

    __half* wl0 = w16 + 0 * (size_t)H_ * H_;
    __half* wl1 = w16 + 1 * (size_t)H_ * H_;
    __half* wl2 = w16 + 2 * (size_t)H_ * H_;

    layer0_act<<<B_ / 2, 256>>>(base0h, tvech, h254, h255, xp, actA);
    for (int i = 0; i < NSTEPS; i++) {
        launch_pdl(gemm_hmma, ggrid, dim3(256), (size_t)GSMEM_TOTAL,
                   (const __half*)actA, (const __half*)wl0, b1, actB);
        launch_pdl(gemm_hmma, ggrid, dim3(256), (size_t)GSMEM_TOTAL,
                   (const __half*)actB, (const __half*)wl1, b2, actA);
        launch_pdl(gemm_hmma_last, ggrid, dim3(256), (size_t)GSMEM_TOTAL,
                   (const __half*)actA, (const __half*)wl2, b3, W4, partp);
        if (i + 1 < NSTEPS) {
            launch_pdl(step_fuse, dim3(B_ / 2), dim3(256), (size_t)0,
                       (const float*)partp, b4, xp, (const __half*)base0h,
                       (const __half*)(tvech + (size_t)(i + 1) * H_), h254, h255, actA);
        } else {
            launch_pdl(out_euler, dim3(B_ / 8), dim3(256), (size_t)0,
                       (const float*)partp, b4, (const float*)xp, out);
        }
    }
}